// round 1
// baseline (speedup 1.0000x reference)
#include <cuda_runtime.h>

#define NN    10000
#define EE    160000
#define TE    (EE + NN)
#define DIN   768
#define DH    128
#define HEADS 4

// ---------------- scratch (static device globals; no allocation) ----------------
__device__ float g_xp   [NN * DH];           // projected x
__device__ float g_gp   [NN * DH];           // projected g
__device__ float g_h1pre[NN * HEADS * DH];   // xp @ gat1_W
__device__ float g_h1   [NN * HEADS * DH];   // after gat1 agg + bias + elu
__device__ float g_h2pre[NN * DH];           // h1 @ gat2_W
__device__ float g_h2   [NN * DH];           // after gat2 agg + bias + beta*gp
__device__ float g_as1  [NN * HEADS];
__device__ float g_ad1  [NN * HEADS];
__device__ float g_as2  [NN];
__device__ float g_ad2  [NN];
__device__ int   g_deg  [NN];
__device__ int   g_off  [NN + 1];
__device__ int   g_cur  [NN];
__device__ int   g_csr  [TE];                // src node ids grouped by dst

// ---------------- CSR build ----------------
__global__ void k_zero_deg() {
    int i = blockIdx.x * blockDim.x + threadIdx.x;
    if (i < NN) g_deg[i] = 0;
}

__global__ void k_count(const int* __restrict__ ei) {
    int i = blockIdx.x * blockDim.x + threadIdx.x;
    if (i < EE) atomicAdd(&g_deg[ei[EE + i]], 1);   // dst row of edge_index
}

// single-block exclusive scan over (deg[i] + 1)  (+1 = self loop)
__global__ void k_scan() {
    __shared__ int sh[1024];
    const int CH = 10;                               // 1024*10 >= NN
    int tid = threadIdx.x;
    int base = tid * CH;
    int s = 0;
#pragma unroll
    for (int j = 0; j < CH; j++) {
        int idx = base + j;
        if (idx < NN) s += g_deg[idx] + 1;
    }
    sh[tid] = s;
    __syncthreads();
    for (int o = 1; o < 1024; o <<= 1) {
        int t = (tid >= o) ? sh[tid - o] : 0;
        __syncthreads();
        sh[tid] += t;
        __syncthreads();
    }
    int run = sh[tid] - s;                           // exclusive prefix
#pragma unroll
    for (int j = 0; j < CH; j++) {
        int idx = base + j;
        if (idx < NN) {
            g_off[idx] = run;
            g_cur[idx] = run;
            run += g_deg[idx] + 1;
        }
    }
    if (tid == 0) g_off[NN] = sh[1023];
}

__global__ void k_fill(const int* __restrict__ ei) {
    int i = blockIdx.x * blockDim.x + threadIdx.x;
    if (i < EE) {
        int d = ei[EE + i];
        int p = atomicAdd(&g_cur[d], 1);
        g_csr[p] = ei[i];
    } else if (i < TE) {
        int n = i - EE;                              // self loop
        int p = atomicAdd(&g_cur[n], 1);
        g_csr[p] = n;
    }
}

// ---------------- tiled fp32 GEMM:  C[M,Nc] = A[M,K] @ B[K,Nc] (+bias) ----------------
#define BM 128
#define BN 128
#define BK 8
#define TM 8
#define TN 8

__global__ __launch_bounds__(256) void k_gemm(const float* __restrict__ A,
                                              const float* __restrict__ B,
                                              const float* __restrict__ bias,
                                              float* __restrict__ C,
                                              int M, int K, int Nc) {
    __shared__ float As[BK][BM + 4];
    __shared__ float Bs[BK][BN + 4];

    int tid = threadIdx.x;
    int tx = tid & 15;
    int ty = tid >> 4;
    int rowBase = blockIdx.y * BM;
    int colBase = blockIdx.x * BN;

    float acc[TM][TN];
#pragma unroll
    for (int i = 0; i < TM; i++)
#pragma unroll
        for (int j = 0; j < TN; j++) acc[i][j] = 0.f;

    int arow = tid >> 1, acol = (tid & 1) * 4;       // A tile: 128 rows x 8 cols
    int brow = tid >> 5, bcol = (tid & 31) * 4;      // B tile: 8 rows x 128 cols

    for (int k0 = 0; k0 < K; k0 += BK) {
        float4 av = make_float4(0.f, 0.f, 0.f, 0.f);
        int gr = rowBase + arow;
        if (gr < M) av = *(const float4*)&A[(size_t)gr * K + k0 + acol];
        As[acol + 0][arow] = av.x;
        As[acol + 1][arow] = av.y;
        As[acol + 2][arow] = av.z;
        As[acol + 3][arow] = av.w;

        float4 bv = *(const float4*)&B[(size_t)(k0 + brow) * Nc + colBase + bcol];
        *(float4*)&Bs[brow][bcol] = bv;
        __syncthreads();

#pragma unroll
        for (int k = 0; k < BK; k++) {
            float af[TM], bf[TN];
#pragma unroll
            for (int i = 0; i < TM; i++) af[i] = As[k][ty * TM + i];
#pragma unroll
            for (int j = 0; j < TN; j++) bf[j] = Bs[k][tx * TN + j];
#pragma unroll
            for (int i = 0; i < TM; i++)
#pragma unroll
                for (int j = 0; j < TN; j++) acc[i][j] += af[i] * bf[j];
        }
        __syncthreads();
    }

#pragma unroll
    for (int i = 0; i < TM; i++) {
        int r = rowBase + ty * TM + i;
        if (r >= M) continue;
#pragma unroll
        for (int j = 0; j < TN; j++) {
            int c = colBase + tx * TN + j;
            float v = acc[i][j];
            if (bias) v += bias[c];
            C[(size_t)r * Nc + c] = v;
        }
    }
}

// ---------------- attention dot products: one warp per (node, head) ----------------
__global__ void k_attdot(const float* __restrict__ h, const float* __restrict__ att_s,
                         const float* __restrict__ att_d,
                         float* __restrict__ outs, float* __restrict__ outd, int H) {
    int gw   = (blockIdx.x * blockDim.x + threadIdx.x) >> 5;
    int lane = threadIdx.x & 31;
    if (gw >= NN * H) return;
    int hh = gw % H;
    float4 x = ((const float4*)h)[(size_t)gw * 32 + lane];
    float4 a = ((const float4*)att_s)[hh * 32 + lane];
    float4 b = ((const float4*)att_d)[hh * 32 + lane];
    float ss = x.x * a.x + x.y * a.y + x.z * a.z + x.w * a.w;
    float dd = x.x * b.x + x.y * b.y + x.z * b.z + x.w * b.w;
#pragma unroll
    for (int o = 16; o; o >>= 1) {
        ss += __shfl_xor_sync(0xffffffffu, ss, o);
        dd += __shfl_xor_sync(0xffffffffu, dd, o);
    }
    if (lane == 0) { outs[gw] = ss; outd[gw] = dd; }
}

__device__ __forceinline__ float lrelu(float e) { return e > 0.f ? e : 0.2f * e; }

// ---------------- GAT1 aggregation: warp per (dst, head), fused bias + ELU ----------------
__global__ void k_agg1(const float* __restrict__ hpre, const float* __restrict__ as_,
                       const float* __restrict__ ad_, const float* __restrict__ bias,
                       float* __restrict__ out) {
    int gw   = (blockIdx.x * blockDim.x + threadIdx.x) >> 5;
    int lane = threadIdx.x & 31;
    if (gw >= NN * HEADS) return;
    int n  = gw / HEADS;
    int hh = gw - n * HEADS;
    int beg = g_off[n], end = g_off[n + 1];
    float adn = ad_[gw];

    // pass 1: segment max (lanes split edges)
    float m = -1e30f;
    for (int i = beg + lane; i < end; i += 32)
        m = fmaxf(m, lrelu(as_[g_csr[i] * HEADS + hh] + adn));
#pragma unroll
    for (int o = 16; o; o >>= 1) m = fmaxf(m, __shfl_xor_sync(0xffffffffu, m, o));

    // pass 2: Σ e^x  and  Σ e^x * h[src]   (lane owns one float4 channel chunk)
    float ws = 0.f;
    float4 acc = make_float4(0.f, 0.f, 0.f, 0.f);
    const float4* h4 = (const float4*)hpre;
    for (int i = beg; i < end; i++) {
        int s = g_csr[i];                             // broadcast load
        float ex = __expf(lrelu(as_[s * HEADS + hh] + adn) - m);
        ws += ex;
        float4 v = h4[(size_t)(s * HEADS + hh) * 32 + lane];
        acc.x += ex * v.x; acc.y += ex * v.y; acc.z += ex * v.z; acc.w += ex * v.w;
    }
    float inv = 1.f / (ws + 1e-16f);
    float4 b = ((const float4*)bias)[hh * 32 + lane];
    float4 o;
    o.x = acc.x * inv + b.x; o.y = acc.y * inv + b.y;
    o.z = acc.z * inv + b.z; o.w = acc.w * inv + b.w;
    o.x = o.x > 0.f ? o.x : expm1f(o.x);
    o.y = o.y > 0.f ? o.y : expm1f(o.y);
    o.z = o.z > 0.f ? o.z : expm1f(o.z);
    o.w = o.w > 0.f ? o.w : expm1f(o.w);
    ((float4*)out)[(size_t)gw * 32 + lane] = o;
}

// ---------------- GAT2 aggregation: warp per dst, fused bias + beta*gp ----------------
__global__ void k_agg2(const float* __restrict__ hpre, const float* __restrict__ as_,
                       const float* __restrict__ ad_, const float* __restrict__ bias,
                       const float* __restrict__ gp, const float* __restrict__ beta,
                       float* __restrict__ out) {
    int n    = (blockIdx.x * blockDim.x + threadIdx.x) >> 5;
    int lane = threadIdx.x & 31;
    if (n >= NN) return;
    int beg = g_off[n], end = g_off[n + 1];
    float adn = ad_[n];

    float m = -1e30f;
    for (int i = beg + lane; i < end; i += 32)
        m = fmaxf(m, lrelu(as_[g_csr[i]] + adn));
#pragma unroll
    for (int o = 16; o; o >>= 1) m = fmaxf(m, __shfl_xor_sync(0xffffffffu, m, o));

    float ws = 0.f;
    float4 acc = make_float4(0.f, 0.f, 0.f, 0.f);
    const float4* h4 = (const float4*)hpre;
    for (int i = beg; i < end; i++) {
        int s = g_csr[i];
        float ex = __expf(lrelu(as_[s] + adn) - m);
        ws += ex;
        float4 v = h4[(size_t)s * 32 + lane];
        acc.x += ex * v.x; acc.y += ex * v.y; acc.z += ex * v.z; acc.w += ex * v.w;
    }
    float inv = 1.f / (ws + 1e-16f);
    float bt = *beta;
    float4 b = ((const float4*)bias)[lane];
    float4 gv = ((const float4*)gp)[(size_t)n * 32 + lane];
    float4 o;
    o.x = acc.x * inv + b.x + bt * gv.x;
    o.y = acc.y * inv + b.y + bt * gv.y;
    o.z = acc.z * inv + b.z + bt * gv.z;
    o.w = acc.w * inv + b.w + bt * gv.w;
    ((float4*)out)[(size_t)n * 32 + lane] = o;
}

// ---------------- launch ----------------
extern "C" void kernel_launch(void* const* d_in, const int* in_sizes, int n_in,
                              void* d_out, int out_size) {
    const float* x      = (const float*)d_in[0];
    const int*   ei     = (const int*)  d_in[1];
    const float* g      = (const float*)d_in[2];
    const float* proj_W = (const float*)d_in[3];
    const float* proj_b = (const float*)d_in[4];
    const float* g1_W   = (const float*)d_in[5];
    const float* g1_as  = (const float*)d_in[6];
    const float* g1_ad  = (const float*)d_in[7];
    const float* g1_b   = (const float*)d_in[8];
    const float* g2_W   = (const float*)d_in[9];
    const float* g2_as  = (const float*)d_in[10];
    const float* g2_ad  = (const float*)d_in[11];
    const float* g2_b   = (const float*)d_in[12];
    const float* dec_W  = (const float*)d_in[13];
    const float* dec_b  = (const float*)d_in[14];
    const float* beta   = (const float*)d_in[15];
    float* out = (float*)d_out;

    float *xp, *gp, *h1pre, *h1, *h2pre, *h2, *as1, *ad1, *as2, *ad2;
    cudaGetSymbolAddress((void**)&xp,    g_xp);
    cudaGetSymbolAddress((void**)&gp,    g_gp);
    cudaGetSymbolAddress((void**)&h1pre, g_h1pre);
    cudaGetSymbolAddress((void**)&h1,    g_h1);
    cudaGetSymbolAddress((void**)&h2pre, g_h2pre);
    cudaGetSymbolAddress((void**)&h2,    g_h2);
    cudaGetSymbolAddress((void**)&as1,   g_as1);
    cudaGetSymbolAddress((void**)&ad1,   g_ad1);
    cudaGetSymbolAddress((void**)&as2,   g_as2);
    cudaGetSymbolAddress((void**)&ad2,   g_ad2);

    const int MB = (NN + BM - 1) / BM;   // 79

    // CSR build (independent of GEMM chain; stream-ordered anyway)
    k_zero_deg<<<(NN + 255) / 256, 256>>>();
    k_count<<<(EE + 255) / 256, 256>>>(ei);
    k_scan<<<1, 1024>>>();
    k_fill<<<(TE + 255) / 256, 256>>>(ei);

    // projections
    k_gemm<<<dim3(DH / BN, MB), 256>>>(x, proj_W, proj_b, xp, NN, DIN, DH);
    k_gemm<<<dim3(DH / BN, MB), 256>>>(g, proj_W, proj_b, gp, NN, DIN, DH);

    // GAT1
    k_gemm<<<dim3(HEADS * DH / BN, MB), 256>>>(xp, g1_W, nullptr, h1pre, NN, DH, HEADS * DH);
    k_attdot<<<(NN * HEADS * 32 + 255) / 256, 256>>>(h1pre, g1_as, g1_ad, as1, ad1, HEADS);
    k_agg1<<<(NN * HEADS * 32 + 255) / 256, 256>>>(h1pre, as1, ad1, g1_b, h1);

    // GAT2
    k_gemm<<<dim3(DH / BN, MB), 256>>>(h1, g2_W, nullptr, h2pre, NN, HEADS * DH, DH);
    k_attdot<<<(NN * 32 + 255) / 256, 256>>>(h2pre, g2_as, g2_ad, as2, ad2, 1);
    k_agg2<<<(NN * 32 + 255) / 256, 256>>>(h2pre, as2, ad2, g2_b, gp, beta, h2);

    // decoder
    k_gemm<<<dim3(DIN / BN, MB), 256>>>(h2, dec_W, dec_b, out, NN, DH, DIN);
}

// round 5
// speedup vs baseline: 2.2456x; 2.2456x over previous
#include <cuda_runtime.h>
#include <cuda_bf16.h>
#include <cstdint>

#define NN    10000
#define EE    160000
#define TE    (EE + NN)
#define DIN   768
#define DH    128
#define HEADS 4
#define MP    (2 * NN)           // batched proj rows (x then g)

// ---------------- scratch (static device globals) ----------------
__device__ __align__(256) __nv_bfloat16 g_xg_hi[MP * DIN], g_xg_lo[MP * DIN];
__device__ __align__(256) float         g_xpgp[MP * DH];
__device__ __align__(256) __nv_bfloat16 g_xpgp_hi[MP * DH], g_xpgp_lo[MP * DH];
__device__ __align__(256) float         g_h1pre[NN * HEADS * DH];
__device__ __align__(256) __nv_bfloat16 g_h1_hi[NN * HEADS * DH], g_h1_lo[NN * HEADS * DH];
__device__ __align__(256) float         g_h2pre[NN * DH];
__device__ __align__(256) __nv_bfloat16 g_h2_hi[NN * DH], g_h2_lo[NN * DH];
// transposed + split weights: Bt[n][k]
__device__ __align__(256) __nv_bfloat16 g_wp_hi[DH * DIN],        g_wp_lo[DH * DIN];
__device__ __align__(256) __nv_bfloat16 g_w1_hi[HEADS * DH * DH], g_w1_lo[HEADS * DH * DH];
__device__ __align__(256) __nv_bfloat16 g_w2_hi[DH * HEADS * DH], g_w2_lo[DH * HEADS * DH];
__device__ __align__(256) __nv_bfloat16 g_wd_hi[DIN * DH],        g_wd_lo[DIN * DH];
__device__ float g_as1[NN * HEADS], g_ad1[NN * HEADS], g_as2[NN], g_ad2[NN];
__device__ int   g_deg[NN], g_off[NN + 1], g_cur[NN], g_csr[TE];

// ---------------- helpers ----------------
__device__ __forceinline__ uint32_t smem_u32(const void* p) {
    uint32_t a;
    asm("{ .reg .u64 t; cvta.to.shared.u64 t, %1; cvt.u32.u64 %0, t; }" : "=r"(a) : "l"(p));
    return a;
}
__device__ __forceinline__ void cp16(uint32_t dst, const void* src) {
    asm volatile("cp.async.cg.shared.global [%0], [%1], 16;" :: "r"(dst), "l"(src));
}
#define CP_COMMIT() asm volatile("cp.async.commit_group;" ::: "memory")
#define CP_WAIT1()  asm volatile("cp.async.wait_group 1;" ::: "memory")
#define CP_WAIT0()  asm volatile("cp.async.wait_group 0;" ::: "memory")

__device__ __forceinline__ void mma_bf16(float* c, uint32_t a0, uint32_t a1, uint32_t a2, uint32_t a3,
                                         uint32_t b0, uint32_t b1) {
    asm volatile("mma.sync.aligned.m16n8k16.row.col.f32.bf16.bf16.f32 "
                 "{%0,%1,%2,%3}, {%4,%5,%6,%7}, {%8,%9}, {%0,%1,%2,%3};"
                 : "+f"(c[0]), "+f"(c[1]), "+f"(c[2]), "+f"(c[3])
                 : "r"(a0), "r"(a1), "r"(a2), "r"(a3), "r"(b0), "r"(b1));
}
__device__ __forceinline__ uint32_t lds32(uint32_t a) {
    uint32_t r;
    asm volatile("ld.shared.b32 %0, [%1];" : "=r"(r) : "r"(a));
    return r;
}

// ---------------- CSR build ----------------
__global__ void k_zero_deg() {
    int i = blockIdx.x * blockDim.x + threadIdx.x;
    if (i < NN) g_deg[i] = 0;
}
__global__ void k_count(const int* __restrict__ ei) {
    int i = blockIdx.x * blockDim.x + threadIdx.x;
    if (i < EE) atomicAdd(&g_deg[ei[EE + i]], 1);
}
__global__ void k_scan() {
    __shared__ int sh[1024];
    const int CH = 10;
    int tid = threadIdx.x, base = tid * CH, s = 0;
#pragma unroll
    for (int j = 0; j < CH; j++) { int idx = base + j; if (idx < NN) s += g_deg[idx] + 1; }
    sh[tid] = s;
    __syncthreads();
    for (int o = 1; o < 1024; o <<= 1) {
        int t = (tid >= o) ? sh[tid - o] : 0;
        __syncthreads();
        sh[tid] += t;
        __syncthreads();
    }
    int run = sh[tid] - s;
#pragma unroll
    for (int j = 0; j < CH; j++) {
        int idx = base + j;
        if (idx < NN) { g_off[idx] = run; g_cur[idx] = run; run += g_deg[idx] + 1; }
    }
    if (tid == 0) g_off[NN] = sh[1023];
}
__global__ void k_fill(const int* __restrict__ ei) {
    int i = blockIdx.x * blockDim.x + threadIdx.x;
    if (i < EE) {
        int d = ei[EE + i];
        g_csr[atomicAdd(&g_cur[d], 1)] = ei[i];
    } else if (i < TE) {
        int n = i - EE;
        g_csr[atomicAdd(&g_cur[n], 1)] = n;
    }
}

// ---------------- fp32 -> bf16 hi/lo split ----------------
__global__ void k_split(const float* __restrict__ in, __nv_bfloat16* __restrict__ hi,
                        __nv_bfloat16* __restrict__ lo, int n4) {
    int i = blockIdx.x * blockDim.x + threadIdx.x;
    if (i >= n4) return;
    float4 v = ((const float4*)in)[i];
    __nv_bfloat162 h01, h23, l01, l23;
    h01.x = __float2bfloat16(v.x); l01.x = __float2bfloat16(v.x - __bfloat162float(h01.x));
    h01.y = __float2bfloat16(v.y); l01.y = __float2bfloat16(v.y - __bfloat162float(h01.y));
    h23.x = __float2bfloat16(v.z); l23.x = __float2bfloat16(v.z - __bfloat162float(h23.x));
    h23.y = __float2bfloat16(v.w); l23.y = __float2bfloat16(v.w - __bfloat162float(h23.y));
    ((__nv_bfloat162*)hi)[i * 2] = h01; ((__nv_bfloat162*)hi)[i * 2 + 1] = h23;
    ((__nv_bfloat162*)lo)[i * 2] = l01; ((__nv_bfloat162*)lo)[i * 2 + 1] = l23;
}

// weight transpose + split: W[K][N] -> Bt[N][K] hi/lo
__global__ void k_wsplit(const float* __restrict__ W, __nv_bfloat16* __restrict__ bh,
                         __nv_bfloat16* __restrict__ bl, int K, int N) {
    int i = blockIdx.x * blockDim.x + threadIdx.x;
    if (i >= K * N) return;
    int k = i / N, n = i - k * N;
    float v = W[i];
    __nv_bfloat16 h = __float2bfloat16(v);
    bh[(size_t)n * K + k] = h;
    bl[(size_t)n * K + k] = __float2bfloat16(v - __bfloat162float(h));
}

// ---------------- mma.sync bf16x3 GEMM: C[M,Nc] = A @ Bt^T ----------------
// SMEM stage layout (halves row stride RS=40 words -> 80 B):
//   Ah @ 0, Al @ 10240, Bh @ 20480, Bl @ 30720 ; stage size 40960 B, x2 stages
#define RS_B   80
#define ARR_B  10240
#define STAGE_B 40960
#define GSMEM  (2 * STAGE_B)

__global__ __launch_bounds__(256, 1) void k_gemm_mma(
    const __nv_bfloat16* __restrict__ Ahi, const __nv_bfloat16* __restrict__ Alo,
    const __nv_bfloat16* __restrict__ Bhi, const __nv_bfloat16* __restrict__ Blo,
    const float* __restrict__ bias,
    float* __restrict__ Cf, __nv_bfloat16* __restrict__ Chi, __nv_bfloat16* __restrict__ Clo,
    int M, int K, int Nc)
{
    extern __shared__ char smem[];
    const uint32_t sb = smem_u32(smem);
    const int tid = threadIdx.x, wid = tid >> 5, lane = tid & 31;
    const int gid = lane >> 2, tig = lane & 3;
    const int mBase = blockIdx.y * 128, nBase = blockIdx.x * 128;
    const int wrow = (wid & 1) * 64, wcol = (wid >> 1) * 32;

    float acc[4][4][4];
#pragma unroll
    for (int i = 0; i < 4; i++)
#pragma unroll
        for (int j = 0; j < 4; j++)
#pragma unroll
            for (int q = 0; q < 4; q++) acc[i][j][q] = 0.f;

    const int nchunk = K >> 5;

    // stage fill: 512 16B-chunks per array, 2 per thread
    const int r0 = tid >> 2, seg0 = tid & 3;            // chunk ids tid and tid+256
    const int r1 = (tid + 256) >> 2, seg1 = (tid + 256) & 3;

#define FILL_STAGE(bufbase, k0) do {                                            \
        {   uint32_t so = (uint32_t)(r0 * RS_B + seg0 * 16);                    \
            int ra = mBase + r0; if (ra > M - 1) ra = M - 1;                    \
            size_t ea = (size_t)ra * K + (k0) + seg0 * 8;                       \
            size_t eb = (size_t)(nBase + r0) * K + (k0) + seg0 * 8;             \
            cp16((bufbase) + so,             Ahi + ea);                         \
            cp16((bufbase) + ARR_B + so,     Alo + ea);                         \
            cp16((bufbase) + 2 * ARR_B + so, Bhi + eb);                         \
            cp16((bufbase) + 3 * ARR_B + so, Blo + eb); }                       \
        {   uint32_t so = (uint32_t)(r1 * RS_B + seg1 * 16);                    \
            int ra = mBase + r1; if (ra > M - 1) ra = M - 1;                    \
            size_t ea = (size_t)ra * K + (k0) + seg1 * 8;                       \
            size_t eb = (size_t)(nBase + r1) * K + (k0) + seg1 * 8;             \
            cp16((bufbase) + so,             Ahi + ea);                         \
            cp16((bufbase) + ARR_B + so,     Alo + ea);                         \
            cp16((bufbase) + 2 * ARR_B + so, Bhi + eb);                         \
            cp16((bufbase) + 3 * ARR_B + so, Blo + eb); }                       \
    } while (0)

    FILL_STAGE(sb, 0);
    CP_COMMIT();

    for (int c = 0; c < nchunk; c++) {
        if (c + 1 < nchunk) {
            FILL_STAGE(sb + ((c + 1) & 1) * STAGE_B, (c + 1) << 5);
            CP_COMMIT();
            CP_WAIT1();
        } else {
            CP_WAIT0();
        }
        __syncthreads();

        const uint32_t sbuf = sb + (c & 1) * STAGE_B;
        const uint32_t aB = sbuf + (uint32_t)((wrow + gid) * RS_B + tig * 4);
        const uint32_t bB = sbuf + 2 * ARR_B + (uint32_t)((wcol + gid) * RS_B + tig * 4);

#pragma unroll
        for (int ks = 0; ks < 2; ks++) {
            const uint32_t ko = ks * 32;
            uint32_t ah[4][4], al[4][4], bh[4][2], bl[4][2];
#pragma unroll
            for (int mt = 0; mt < 4; mt++) {
                uint32_t p = aB + mt * (16 * RS_B) + ko;
                ah[mt][0] = lds32(p);           ah[mt][1] = lds32(p + 8 * RS_B);
                ah[mt][2] = lds32(p + 16);      ah[mt][3] = lds32(p + 8 * RS_B + 16);
                al[mt][0] = lds32(p + ARR_B);       al[mt][1] = lds32(p + ARR_B + 8 * RS_B);
                al[mt][2] = lds32(p + ARR_B + 16);  al[mt][3] = lds32(p + ARR_B + 8 * RS_B + 16);
            }
#pragma unroll
            for (int nt = 0; nt < 4; nt++) {
                uint32_t p = bB + nt * (8 * RS_B) + ko;
                bh[nt][0] = lds32(p);        bh[nt][1] = lds32(p + 16);
                bl[nt][0] = lds32(p + ARR_B); bl[nt][1] = lds32(p + ARR_B + 16);
            }
#pragma unroll
            for (int mt = 0; mt < 4; mt++)
#pragma unroll
                for (int nt = 0; nt < 4; nt++) {
                    mma_bf16(acc[mt][nt], ah[mt][0], ah[mt][1], ah[mt][2], ah[mt][3], bh[nt][0], bh[nt][1]);
                    mma_bf16(acc[mt][nt], ah[mt][0], ah[mt][1], ah[mt][2], ah[mt][3], bl[nt][0], bl[nt][1]);
                    mma_bf16(acc[mt][nt], al[mt][0], al[mt][1], al[mt][2], al[mt][3], bh[nt][0], bh[nt][1]);
                }
        }
        __syncthreads();
    }

    // epilogue
#pragma unroll
    for (int mt = 0; mt < 4; mt++) {
        int row0 = mBase + wrow + mt * 16 + gid;
#pragma unroll
        for (int half = 0; half < 2; half++) {
            int row = row0 + half * 8;
            if (row >= M) continue;
#pragma unroll
            for (int nt = 0; nt < 4; nt++) {
                int col = nBase + wcol + nt * 8 + tig * 2;
                float v0 = acc[mt][nt][half * 2 + 0];
                float v1 = acc[mt][nt][half * 2 + 1];
                if (bias) { v0 += bias[col]; v1 += bias[col + 1]; }
                size_t oi = (size_t)row * Nc + col;
                if (Cf) *(float2*)(Cf + oi) = make_float2(v0, v1);
                if (Chi) {
                    __nv_bfloat162 h, l;
                    h.x = __float2bfloat16(v0); l.x = __float2bfloat16(v0 - __bfloat162float(h.x));
                    h.y = __float2bfloat16(v1); l.y = __float2bfloat16(v1 - __bfloat162float(h.y));
                    *(__nv_bfloat162*)(Chi + oi) = h;
                    *(__nv_bfloat162*)(Clo + oi) = l;
                }
            }
        }
    }
#undef FILL_STAGE
}

// ---------------- attention dots ----------------
__global__ void k_attdot(const float* __restrict__ h, const float* __restrict__ att_s,
                         const float* __restrict__ att_d,
                         float* __restrict__ outs, float* __restrict__ outd, int H) {
    int gw = (blockIdx.x * blockDim.x + threadIdx.x) >> 5;
    int lane = threadIdx.x & 31;
    if (gw >= NN * H) return;
    int hh = gw % H;
    float4 x = ((const float4*)h)[(size_t)gw * 32 + lane];
    float4 a = ((const float4*)att_s)[hh * 32 + lane];
    float4 b = ((const float4*)att_d)[hh * 32 + lane];
    float ss = x.x * a.x + x.y * a.y + x.z * a.z + x.w * a.w;
    float dd = x.x * b.x + x.y * b.y + x.z * b.z + x.w * b.w;
#pragma unroll
    for (int o = 16; o; o >>= 1) {
        ss += __shfl_xor_sync(0xffffffffu, ss, o);
        dd += __shfl_xor_sync(0xffffffffu, dd, o);
    }
    if (lane == 0) { outs[gw] = ss; outd[gw] = dd; }
}

__device__ __forceinline__ float lrelu(float e) { return e > 0.f ? e : 0.2f * e; }

// ---------------- GAT1 agg: bias + ELU + bf16 split out ----------------
__global__ void k_agg1(const float* __restrict__ hpre, const float* __restrict__ as_,
                       const float* __restrict__ ad_, const float* __restrict__ bias,
                       __nv_bfloat16* __restrict__ ohi, __nv_bfloat16* __restrict__ olo) {
    int gw = (blockIdx.x * blockDim.x + threadIdx.x) >> 5;
    int lane = threadIdx.x & 31;
    if (gw >= NN * HEADS) return;
    int n = gw / HEADS, hh = gw - n * HEADS;
    int beg = g_off[n], end = g_off[n + 1];
    float adn = ad_[gw];

    float m = -1e30f;
    for (int i = beg + lane; i < end; i += 32)
        m = fmaxf(m, lrelu(as_[g_csr[i] * HEADS + hh] + adn));
#pragma unroll
    for (int o = 16; o; o >>= 1) m = fmaxf(m, __shfl_xor_sync(0xffffffffu, m, o));

    float ws = 0.f;
    float4 acc = make_float4(0.f, 0.f, 0.f, 0.f);
    const float4* h4 = (const float4*)hpre;
    for (int i = beg; i < end; i++) {
        int s = g_csr[i];
        float ex = __expf(lrelu(as_[s * HEADS + hh] + adn) - m);
        ws += ex;
        float4 v = h4[(size_t)(s * HEADS + hh) * 32 + lane];
        acc.x += ex * v.x; acc.y += ex * v.y; acc.z += ex * v.z; acc.w += ex * v.w;
    }
    float inv = 1.f / (ws + 1e-16f);
    float4 b = ((const float4*)bias)[hh * 32 + lane];
    float4 o;
    o.x = acc.x * inv + b.x; o.y = acc.y * inv + b.y;
    o.z = acc.z * inv + b.z; o.w = acc.w * inv + b.w;
    o.x = o.x > 0.f ? o.x : expm1f(o.x);
    o.y = o.y > 0.f ? o.y : expm1f(o.y);
    o.z = o.z > 0.f ? o.z : expm1f(o.z);
    o.w = o.w > 0.f ? o.w : expm1f(o.w);
    size_t oi = (size_t)gw * 128 + lane * 4;
    __nv_bfloat162 h01, h23, l01, l23;
    h01.x = __float2bfloat16(o.x); l01.x = __float2bfloat16(o.x - __bfloat162float(h01.x));
    h01.y = __float2bfloat16(o.y); l01.y = __float2bfloat16(o.y - __bfloat162float(h01.y));
    h23.x = __float2bfloat16(o.z); l23.x = __float2bfloat16(o.z - __bfloat162float(h23.x));
    h23.y = __float2bfloat16(o.w); l23.y = __float2bfloat16(o.w - __bfloat162float(h23.y));
    *(__nv_bfloat162*)(ohi + oi) = h01; *(__nv_bfloat162*)(ohi + oi + 2) = h23;
    *(__nv_bfloat162*)(olo + oi) = l01; *(__nv_bfloat162*)(olo + oi + 2) = l23;
}

// ---------------- GAT2 agg: bias + beta*gp + bf16 split out ----------------
__global__ void k_agg2(const float* __restrict__ hpre, const float* __restrict__ as_,
                       const float* __restrict__ ad_, const float* __restrict__ bias,
                       const float* __restrict__ gp, const float* __restrict__ beta,
                       __nv_bfloat16* __restrict__ ohi, __nv_bfloat16* __restrict__ olo) {
    int n = (blockIdx.x * blockDim.x + threadIdx.x) >> 5;
    int lane = threadIdx.x & 31;
    if (n >= NN) return;
    int beg = g_off[n], end = g_off[n + 1];
    float adn = ad_[n];

    float m = -1e30f;
    for (int i = beg + lane; i < end; i += 32)
        m = fmaxf(m, lrelu(as_[g_csr[i]] + adn));
#pragma unroll
    for (int o = 16; o; o >>= 1) m = fmaxf(m, __shfl_xor_sync(0xffffffffu, m, o));

    float ws = 0.f;
    float4 acc = make_float4(0.f, 0.f, 0.f, 0.f);
    const float4* h4 = (const float4*)hpre;
    for (int i = beg; i < end; i++) {
        int s = g_csr[i];
        float ex = __expf(lrelu(as_[s] + adn) - m);
        ws += ex;
        float4 v = h4[(size_t)s * 32 + lane];
        acc.x += ex * v.x; acc.y += ex * v.y; acc.z += ex * v.z; acc.w += ex * v.w;
    }
    float inv = 1.f / (ws + 1e-16f);
    float bt = *beta;
    float4 b = ((const float4*)bias)[lane];
    float4 gv = ((const float4*)gp)[(size_t)n * 32 + lane];
    float4 o;
    o.x = acc.x * inv + b.x + bt * gv.x;
    o.y = acc.y * inv + b.y + bt * gv.y;
    o.z = acc.z * inv + b.z + bt * gv.z;
    o.w = acc.w * inv + b.w + bt * gv.w;
    size_t oi = (size_t)n * 128 + lane * 4;
    __nv_bfloat162 h01, h23, l01, l23;
    h01.x = __float2bfloat16(o.x); l01.x = __float2bfloat16(o.x - __bfloat162float(h01.x));
    h01.y = __float2bfloat16(o.y); l01.y = __float2bfloat16(o.y - __bfloat162float(h01.y));
    h23.x = __float2bfloat16(o.z); l23.x = __float2bfloat16(o.z - __bfloat162float(h23.x));
    h23.y = __float2bfloat16(o.w); l23.y = __float2bfloat16(o.w - __bfloat162float(h23.y));
    *(__nv_bfloat162*)(ohi + oi) = h01; *(__nv_bfloat162*)(ohi + oi + 2) = h23;
    *(__nv_bfloat162*)(olo + oi) = l01; *(__nv_bfloat162*)(olo + oi + 2) = l23;
}

// ---------------- launch ----------------
extern "C" void kernel_launch(void* const* d_in, const int* in_sizes, int n_in,
                              void* d_out, int out_size) {
    const float* x      = (const float*)d_in[0];
    const int*   ei     = (const int*)  d_in[1];
    const float* g      = (const float*)d_in[2];
    const float* proj_W = (const float*)d_in[3];
    const float* proj_b = (const float*)d_in[4];
    const float* g1_W   = (const float*)d_in[5];
    const float* g1_as  = (const float*)d_in[6];
    const float* g1_ad  = (const float*)d_in[7];
    const float* g1_b   = (const float*)d_in[8];
    const float* g2_W   = (const float*)d_in[9];
    const float* g2_as  = (const float*)d_in[10];
    const float* g2_ad  = (const float*)d_in[11];
    const float* g2_b   = (const float*)d_in[12];
    const float* dec_W  = (const float*)d_in[13];
    const float* dec_b  = (const float*)d_in[14];
    const float* beta   = (const float*)d_in[15];
    float* out = (float*)d_out;

    __nv_bfloat16 *xg_hi, *xg_lo, *xpgp_hi, *xpgp_lo, *h1_hi, *h1_lo, *h2_hi, *h2_lo;
    __nv_bfloat16 *wp_hi, *wp_lo, *w1_hi, *w1_lo, *w2_hi, *w2_lo, *wd_hi, *wd_lo;
    float *xpgp, *h1pre, *h2pre, *as1, *ad1, *as2, *ad2;
    cudaGetSymbolAddress((void**)&xg_hi,   g_xg_hi);   cudaGetSymbolAddress((void**)&xg_lo,   g_xg_lo);
    cudaGetSymbolAddress((void**)&xpgp,    g_xpgp);
    cudaGetSymbolAddress((void**)&xpgp_hi, g_xpgp_hi); cudaGetSymbolAddress((void**)&xpgp_lo, g_xpgp_lo);
    cudaGetSymbolAddress((void**)&h1pre,   g_h1pre);
    cudaGetSymbolAddress((void**)&h1_hi,   g_h1_hi);   cudaGetSymbolAddress((void**)&h1_lo,   g_h1_lo);
    cudaGetSymbolAddress((void**)&h2pre,   g_h2pre);
    cudaGetSymbolAddress((void**)&h2_hi,   g_h2_hi);   cudaGetSymbolAddress((void**)&h2_lo,   g_h2_lo);
    cudaGetSymbolAddress((void**)&wp_hi,   g_wp_hi);   cudaGetSymbolAddress((void**)&wp_lo,   g_wp_lo);
    cudaGetSymbolAddress((void**)&w1_hi,   g_w1_hi);   cudaGetSymbolAddress((void**)&w1_lo,   g_w1_lo);
    cudaGetSymbolAddress((void**)&w2_hi,   g_w2_hi);   cudaGetSymbolAddress((void**)&w2_lo,   g_w2_lo);
    cudaGetSymbolAddress((void**)&wd_hi,   g_wd_hi);   cudaGetSymbolAddress((void**)&wd_lo,   g_wd_lo);
    cudaGetSymbolAddress((void**)&as1, g_as1); cudaGetSymbolAddress((void**)&ad1, g_ad1);
    cudaGetSymbolAddress((void**)&as2, g_as2); cudaGetSymbolAddress((void**)&ad2, g_ad2);

    cudaFuncSetAttribute(k_gemm_mma, cudaFuncAttributeMaxDynamicSharedMemorySize, GSMEM);

    // CSR
    k_zero_deg<<<(NN + 255) / 256, 256>>>();
    k_count<<<(EE + 255) / 256, 256>>>(ei);
    k_scan<<<1, 1024>>>();
    k_fill<<<(TE + 255) / 256, 256>>>(ei);

    // input splits
    {
        int n4 = NN * DIN / 4;
        k_split<<<(n4 + 255) / 256, 256>>>(x, xg_hi, xg_lo, n4);
        k_split<<<(n4 + 255) / 256, 256>>>(g, xg_hi + (size_t)NN * DIN, xg_lo + (size_t)NN * DIN, n4);
    }
    // weight transpose + split
    k_wsplit<<<(DIN * DH + 255) / 256, 256>>>(proj_W, wp_hi, wp_lo, DIN, DH);
    k_wsplit<<<(DH * HEADS * DH + 255) / 256, 256>>>(g1_W, w1_hi, w1_lo, DH, HEADS * DH);
    k_wsplit<<<(HEADS * DH * DH + 255) / 256, 256>>>(g2_W, w2_hi, w2_lo, HEADS * DH, DH);
    k_wsplit<<<(DH * DIN + 255) / 256, 256>>>(dec_W, wd_hi, wd_lo, DH, DIN);

    // proj (batched x|g): [20000,768] @ [768,128]
    k_gemm_mma<<<dim3(1, (MP + 127) / 128), 256, GSMEM>>>(
        xg_hi, xg_lo, wp_hi, wp_lo, proj_b, xpgp, xpgp_hi, xpgp_lo, MP, DIN, DH);

    // GAT1: [10000,128] @ [128,512]
    k_gemm_mma<<<dim3(HEADS * DH / 128, (NN + 127) / 128), 256, GSMEM>>>(
        xpgp_hi, xpgp_lo, w1_hi, w1_lo, nullptr, h1pre, nullptr, nullptr, NN, DH, HEADS * DH);
    k_attdot<<<(NN * HEADS * 32 + 255) / 256, 256>>>(h1pre, g1_as, g1_ad, as1, ad1, HEADS);
    k_agg1<<<(NN * HEADS * 32 + 255) / 256, 256>>>(h1pre, as1, ad1, g1_b, h1_hi, h1_lo);

    // GAT2: [10000,512] @ [512,128]
    k_gemm_mma<<<dim3(1, (NN + 127) / 128), 256, GSMEM>>>(
        h1_hi, h1_lo, w2_hi, w2_lo, nullptr, h2pre, nullptr, nullptr, NN, HEADS * DH, DH);
    k_attdot<<<(NN * 32 + 255) / 256, 256>>>(h2pre, g2_as, g2_ad, as2, ad2, 1);
    k_agg2<<<(NN * 32 + 255) / 256, 256>>>(h2pre, as2, ad2, g2_b, xpgp + (size_t)NN * DH, beta, h2_hi, h2_lo);

    // decoder: [10000,128] @ [128,768]
    k_gemm_mma<<<dim3(DIN / 128, (NN + 127) / 128), 256, GSMEM>>>(
        h2_hi, h2_lo, wd_hi, wd_lo, dec_b, out, nullptr, nullptr, NN, DH, DIN);
}

// round 6
// speedup vs baseline: 2.2637x; 1.0080x over previous
#include <cuda_runtime.h>
#include <cuda_bf16.h>
#include <cstdint>

#define NN    10000
#define EE    160000
#define TE    (EE + NN)
#define DIN   768
#define DH    128
#define HEADS 4
#define MP    (2 * NN)           // batched proj rows (x then g)

// ---------------- scratch (static device globals) ----------------
__device__ __align__(256) __nv_bfloat16 g_xg_hi[MP * DIN], g_xg_lo[MP * DIN];
__device__ __align__(256) float         g_xpgp[MP * DH];
__device__ __align__(256) __nv_bfloat16 g_xpgp_hi[MP * DH], g_xpgp_lo[MP * DH];
__device__ __align__(256) float         g_h1pre[NN * HEADS * DH];
__device__ __align__(256) __nv_bfloat16 g_h1_hi[NN * HEADS * DH], g_h1_lo[NN * HEADS * DH];
__device__ __align__(256) float         g_h2pre[NN * DH];
__device__ __align__(256) __nv_bfloat16 g_h2_hi[NN * DH], g_h2_lo[NN * DH];
// transposed + split weights: Bt[n][k]
__device__ __align__(256) __nv_bfloat16 g_wp_hi[DH * DIN],        g_wp_lo[DH * DIN];
__device__ __align__(256) __nv_bfloat16 g_w1_hi[HEADS * DH * DH], g_w1_lo[HEADS * DH * DH];
__device__ __align__(256) __nv_bfloat16 g_w2_hi[DH * HEADS * DH], g_w2_lo[DH * HEADS * DH];
__device__ __align__(256) __nv_bfloat16 g_wd_hi[DIN * DH],        g_wd_lo[DIN * DH];
__device__ float g_as1[NN * HEADS], g_ad1[NN * HEADS], g_as2[NN], g_ad2[NN];
__device__ int   g_deg[NN], g_off[NN + 1], g_cur[NN], g_csr[TE];

// ---------------- helpers ----------------
__device__ __forceinline__ uint32_t smem_u32(const void* p) {
    uint32_t a;
    asm("{ .reg .u64 t; cvta.to.shared.u64 t, %1; cvt.u32.u64 %0, t; }" : "=r"(a) : "l"(p));
    return a;
}
__device__ __forceinline__ void cp16(uint32_t dst, const void* src) {
    asm volatile("cp.async.cg.shared.global [%0], [%1], 16;" :: "r"(dst), "l"(src));
}
#define CP_COMMIT() asm volatile("cp.async.commit_group;" ::: "memory")
#define CP_WAIT1()  asm volatile("cp.async.wait_group 1;" ::: "memory")
#define CP_WAIT0()  asm volatile("cp.async.wait_group 0;" ::: "memory")

__device__ __forceinline__ void mma_bf16(float* c, uint32_t a0, uint32_t a1, uint32_t a2, uint32_t a3,
                                         uint32_t b0, uint32_t b1) {
    asm volatile("mma.sync.aligned.m16n8k16.row.col.f32.bf16.bf16.f32 "
                 "{%0,%1,%2,%3}, {%4,%5,%6,%7}, {%8,%9}, {%0,%1,%2,%3};"
                 : "+f"(c[0]), "+f"(c[1]), "+f"(c[2]), "+f"(c[3])
                 : "r"(a0), "r"(a1), "r"(a2), "r"(a3), "r"(b0), "r"(b1));
}
__device__ __forceinline__ void ldsm4(uint32_t* r, uint32_t addr) {
    asm volatile("ldmatrix.sync.aligned.m8n8.x4.shared.b16 {%0,%1,%2,%3}, [%4];"
                 : "=r"(r[0]), "=r"(r[1]), "=r"(r[2]), "=r"(r[3]) : "r"(addr));
}

// ---------------- CSR build ----------------
__global__ void k_zero_deg() {
    int i = blockIdx.x * blockDim.x + threadIdx.x;
    if (i < NN) g_deg[i] = 0;
}
__global__ void k_count(const int* __restrict__ ei) {
    int i = blockIdx.x * blockDim.x + threadIdx.x;
    if (i < EE) atomicAdd(&g_deg[ei[EE + i]], 1);
}
__global__ void k_scan() {
    __shared__ int sh[1024];
    const int CH = 10;
    int tid = threadIdx.x, base = tid * CH, s = 0;
#pragma unroll
    for (int j = 0; j < CH; j++) { int idx = base + j; if (idx < NN) s += g_deg[idx] + 1; }
    sh[tid] = s;
    __syncthreads();
    for (int o = 1; o < 1024; o <<= 1) {
        int t = (tid >= o) ? sh[tid - o] : 0;
        __syncthreads();
        sh[tid] += t;
        __syncthreads();
    }
    int run = sh[tid] - s;
#pragma unroll
    for (int j = 0; j < CH; j++) {
        int idx = base + j;
        if (idx < NN) { g_off[idx] = run; g_cur[idx] = run; run += g_deg[idx] + 1; }
    }
    if (tid == 0) g_off[NN] = sh[1023];
}
__global__ void k_fill(const int* __restrict__ ei) {
    int i = blockIdx.x * blockDim.x + threadIdx.x;
    if (i < EE) {
        int d = ei[EE + i];
        g_csr[atomicAdd(&g_cur[d], 1)] = ei[i];
    } else if (i < TE) {
        int n = i - EE;
        g_csr[atomicAdd(&g_cur[n], 1)] = n;
    }
}

// ---------------- fp32 -> bf16 hi/lo split ----------------
__global__ void k_split(const float* __restrict__ in, __nv_bfloat16* __restrict__ hi,
                        __nv_bfloat16* __restrict__ lo, int n4) {
    int i = blockIdx.x * blockDim.x + threadIdx.x;
    if (i >= n4) return;
    float4 v = ((const float4*)in)[i];
    __nv_bfloat162 h01, h23, l01, l23;
    h01.x = __float2bfloat16(v.x); l01.x = __float2bfloat16(v.x - __bfloat162float(h01.x));
    h01.y = __float2bfloat16(v.y); l01.y = __float2bfloat16(v.y - __bfloat162float(h01.y));
    h23.x = __float2bfloat16(v.z); l23.x = __float2bfloat16(v.z - __bfloat162float(h23.x));
    h23.y = __float2bfloat16(v.w); l23.y = __float2bfloat16(v.w - __bfloat162float(h23.y));
    ((__nv_bfloat162*)hi)[i * 2] = h01; ((__nv_bfloat162*)hi)[i * 2 + 1] = h23;
    ((__nv_bfloat162*)lo)[i * 2] = l01; ((__nv_bfloat162*)lo)[i * 2 + 1] = l23;
}

// weight transpose + split: W[K][N] -> Bt[N][K] hi/lo
__global__ void k_wsplit(const float* __restrict__ W, __nv_bfloat16* __restrict__ bh,
                         __nv_bfloat16* __restrict__ bl, int K, int N) {
    int i = blockIdx.x * blockDim.x + threadIdx.x;
    if (i >= K * N) return;
    int k = i / N, n = i - k * N;
    float v = W[i];
    __nv_bfloat16 h = __float2bfloat16(v);
    bh[(size_t)n * K + k] = h;
    bl[(size_t)n * K + k] = __float2bfloat16(v - __bfloat162float(h));
}

// ---------------- mma.sync bf16x3 GEMM: C[M,Nc] = A @ Bt^T ----------------
// Row stride 80 B (64 B data + 16 B pad, conflict-free & ldmatrix-compatible).
// Stage: Ah[BM*80] Al[BM*80] Bh[10240] Bl[10240], x2 stages.
#define RS_B   80
#define B_B    10240

template <int MT>     // BM = 32*MT (MT=4 -> 128, MT=2 -> 64)
__global__ __launch_bounds__(256, 1) void k_gemm_mma(
    const __nv_bfloat16* __restrict__ Ahi, const __nv_bfloat16* __restrict__ Alo,
    const __nv_bfloat16* __restrict__ Bhi, const __nv_bfloat16* __restrict__ Blo,
    const float* __restrict__ bias,
    float* __restrict__ Cf, __nv_bfloat16* __restrict__ Chi, __nv_bfloat16* __restrict__ Clo,
    int M, int K, int Nc)
{
    constexpr int BM  = 32 * MT;
    constexpr int A_B = BM * RS_B;
    constexpr int STG = 2 * A_B + 2 * B_B;

    extern __shared__ char smem[];
    const uint32_t sb = smem_u32(smem);
    const int tid = threadIdx.x, wid = tid >> 5, lane = tid & 31;
    const int gid = lane >> 2, tig = lane & 3;
    const int mBase = blockIdx.y * BM, nBase = blockIdx.x * 128;
    const int wrow = (wid & 1) * (16 * MT), wcol = (wid >> 1) * 32;

    float acc[MT][4][4];
#pragma unroll
    for (int i = 0; i < MT; i++)
#pragma unroll
        for (int j = 0; j < 4; j++)
#pragma unroll
            for (int q = 0; q < 4; q++) acc[i][j][q] = 0.f;

    const int nchunk = K >> 5;

    // ldmatrix per-thread base offsets (relative to stage start)
    const uint32_t aOff = (uint32_t)((wrow + (lane & 15)) * RS_B + (lane >> 4) * 16);
    const uint32_t bOff = (uint32_t)(2 * A_B + (wcol + ((lane >> 4) << 3) + (lane & 7)) * RS_B
                                     + ((lane >> 3) & 1) * 16);

    auto fill = [&](uint32_t bufbase, int k0) {
#pragma unroll
        for (int i = tid; i < 4 * BM; i += 256) {
            int row = i >> 2, seg = i & 3;
            uint32_t so = (uint32_t)(row * RS_B + seg * 16);
            int ra = mBase + row; if (ra > M - 1) ra = M - 1;
            size_t ea = (size_t)ra * K + k0 + seg * 8;
            cp16(bufbase + so,       Ahi + ea);
            cp16(bufbase + A_B + so, Alo + ea);
        }
#pragma unroll
        for (int i = tid; i < 512; i += 256) {
            int row = i >> 2, seg = i & 3;
            uint32_t so = (uint32_t)(row * RS_B + seg * 16);
            size_t eb = (size_t)(nBase + row) * K + k0 + seg * 8;
            cp16(bufbase + 2 * A_B + so,       Bhi + eb);
            cp16(bufbase + 2 * A_B + B_B + so, Blo + eb);
        }
    };

    fill(sb, 0);
    CP_COMMIT();

    for (int c = 0; c < nchunk; c++) {
        if (c + 1 < nchunk) {
            fill(sb + ((c + 1) & 1) * STG, (c + 1) << 5);
            CP_COMMIT();
            CP_WAIT1();
        } else {
            CP_WAIT0();
        }
        __syncthreads();

        const uint32_t sbuf = sb + (c & 1) * STG;
        const uint32_t aB = sbuf + aOff;
        const uint32_t bB = sbuf + bOff;

#pragma unroll
        for (int ks = 0; ks < 2; ks++) {
            const uint32_t ko = ks * 32;           // 16 k-elements = 32 bytes
            uint32_t ah[MT][4], al[MT][4], bh[4][2], bl[4][2];
#pragma unroll
            for (int mt = 0; mt < MT; mt++) {
                ldsm4(ah[mt], aB + mt * (16 * RS_B) + ko);
                ldsm4(al[mt], aB + A_B + mt * (16 * RS_B) + ko);
            }
#pragma unroll
            for (int p = 0; p < 2; p++) {          // nt pairs {0,1}, {2,3}
                uint32_t r[4];
                ldsm4(r, bB + p * (16 * RS_B) + ko);
                bh[2 * p][0] = r[0]; bh[2 * p][1] = r[1];
                bh[2 * p + 1][0] = r[2]; bh[2 * p + 1][1] = r[3];
                ldsm4(r, bB + B_B + p * (16 * RS_B) + ko);
                bl[2 * p][0] = r[0]; bl[2 * p][1] = r[1];
                bl[2 * p + 1][0] = r[2]; bl[2 * p + 1][1] = r[3];
            }
#pragma unroll
            for (int mt = 0; mt < MT; mt++)
#pragma unroll
                for (int nt = 0; nt < 4; nt++) {
                    mma_bf16(acc[mt][nt], ah[mt][0], ah[mt][1], ah[mt][2], ah[mt][3], bh[nt][0], bh[nt][1]);
                    mma_bf16(acc[mt][nt], ah[mt][0], ah[mt][1], ah[mt][2], ah[mt][3], bl[nt][0], bl[nt][1]);
                    mma_bf16(acc[mt][nt], al[mt][0], al[mt][1], al[mt][2], al[mt][3], bh[nt][0], bh[nt][1]);
                }
        }
        __syncthreads();
    }

    // epilogue
#pragma unroll
    for (int mt = 0; mt < MT; mt++) {
        int row0 = mBase + wrow + mt * 16 + gid;
#pragma unroll
        for (int half = 0; half < 2; half++) {
            int row = row0 + half * 8;
            if (row >= M) continue;
#pragma unroll
            for (int nt = 0; nt < 4; nt++) {
                int col = nBase + wcol + nt * 8 + tig * 2;
                float v0 = acc[mt][nt][half * 2 + 0];
                float v1 = acc[mt][nt][half * 2 + 1];
                if (bias) { v0 += bias[col]; v1 += bias[col + 1]; }
                size_t oi = (size_t)row * Nc + col;
                if (Cf) *(float2*)(Cf + oi) = make_float2(v0, v1);
                if (Chi) {
                    __nv_bfloat162 h, l;
                    h.x = __float2bfloat16(v0); l.x = __float2bfloat16(v0 - __bfloat162float(h.x));
                    h.y = __float2bfloat16(v1); l.y = __float2bfloat16(v1 - __bfloat162float(h.y));
                    *(__nv_bfloat162*)(Chi + oi) = h;
                    *(__nv_bfloat162*)(Clo + oi) = l;
                }
            }
        }
    }
}

#define GSMEM4 (2 * (2 * 128 * RS_B + 2 * B_B))   // 81920
#define GSMEM2 (2 * (2 * 64  * RS_B + 2 * B_B))   // 61440

// ---------------- attention dots ----------------
__global__ void k_attdot(const float* __restrict__ h, const float* __restrict__ att_s,
                         const float* __restrict__ att_d,
                         float* __restrict__ outs, float* __restrict__ outd, int H) {
    int gw = (blockIdx.x * blockDim.x + threadIdx.x) >> 5;
    int lane = threadIdx.x & 31;
    if (gw >= NN * H) return;
    int hh = gw % H;
    float4 x = ((const float4*)h)[(size_t)gw * 32 + lane];
    float4 a = ((const float4*)att_s)[hh * 32 + lane];
    float4 b = ((const float4*)att_d)[hh * 32 + lane];
    float ss = x.x * a.x + x.y * a.y + x.z * a.z + x.w * a.w;
    float dd = x.x * b.x + x.y * b.y + x.z * b.z + x.w * b.w;
#pragma unroll
    for (int o = 16; o; o >>= 1) {
        ss += __shfl_xor_sync(0xffffffffu, ss, o);
        dd += __shfl_xor_sync(0xffffffffu, dd, o);
    }
    if (lane == 0) { outs[gw] = ss; outd[gw] = dd; }
}

__device__ __forceinline__ float lrelu(float e) { return e > 0.f ? e : 0.2f * e; }

// ---------------- GAT1 agg: bias + ELU + bf16 split out ----------------
__global__ void k_agg1(const float* __restrict__ hpre, const float* __restrict__ as_,
                       const float* __restrict__ ad_, const float* __restrict__ bias,
                       __nv_bfloat16* __restrict__ ohi, __nv_bfloat16* __restrict__ olo) {
    int gw = (blockIdx.x * blockDim.x + threadIdx.x) >> 5;
    int lane = threadIdx.x & 31;
    if (gw >= NN * HEADS) return;
    int n = gw / HEADS, hh = gw - n * HEADS;
    int beg = g_off[n], end = g_off[n + 1];
    float adn = ad_[gw];

    float m = -1e30f;
    for (int i = beg + lane; i < end; i += 32)
        m = fmaxf(m, lrelu(as_[g_csr[i] * HEADS + hh] + adn));
#pragma unroll
    for (int o = 16; o; o >>= 1) m = fmaxf(m, __shfl_xor_sync(0xffffffffu, m, o));

    float ws = 0.f;
    float4 acc = make_float4(0.f, 0.f, 0.f, 0.f);
    const float4* h4 = (const float4*)hpre;
    for (int i = beg; i < end; i++) {
        int s = g_csr[i];
        float ex = __expf(lrelu(as_[s * HEADS + hh] + adn) - m);
        ws += ex;
        float4 v = h4[(size_t)(s * HEADS + hh) * 32 + lane];
        acc.x += ex * v.x; acc.y += ex * v.y; acc.z += ex * v.z; acc.w += ex * v.w;
    }
    float inv = 1.f / (ws + 1e-16f);
    float4 b = ((const float4*)bias)[hh * 32 + lane];
    float4 o;
    o.x = acc.x * inv + b.x; o.y = acc.y * inv + b.y;
    o.z = acc.z * inv + b.z; o.w = acc.w * inv + b.w;
    o.x = o.x > 0.f ? o.x : expm1f(o.x);
    o.y = o.y > 0.f ? o.y : expm1f(o.y);
    o.z = o.z > 0.f ? o.z : expm1f(o.z);
    o.w = o.w > 0.f ? o.w : expm1f(o.w);
    size_t oi = (size_t)gw * 128 + lane * 4;
    __nv_bfloat162 h01, h23, l01, l23;
    h01.x = __float2bfloat16(o.x); l01.x = __float2bfloat16(o.x - __bfloat162float(h01.x));
    h01.y = __float2bfloat16(o.y); l01.y = __float2bfloat16(o.y - __bfloat162float(h01.y));
    h23.x = __float2bfloat16(o.z); l23.x = __float2bfloat16(o.z - __bfloat162float(h23.x));
    h23.y = __float2bfloat16(o.w); l23.y = __float2bfloat16(o.w - __bfloat162float(h23.y));
    *(__nv_bfloat162*)(ohi + oi) = h01; *(__nv_bfloat162*)(ohi + oi + 2) = h23;
    *(__nv_bfloat162*)(olo + oi) = l01; *(__nv_bfloat162*)(olo + oi + 2) = l23;
}

// ---------------- GAT2 agg: bias + beta*gp + bf16 split out ----------------
__global__ void k_agg2(const float* __restrict__ hpre, const float* __restrict__ as_,
                       const float* __restrict__ ad_, const float* __restrict__ bias,
                       const float* __restrict__ gp, const float* __restrict__ beta,
                       __nv_bfloat16* __restrict__ ohi, __nv_bfloat16* __restrict__ olo) {
    int n = (blockIdx.x * blockDim.x + threadIdx.x) >> 5;
    int lane = threadIdx.x & 31;
    if (n >= NN) return;
    int beg = g_off[n], end = g_off[n + 1];
    float adn = ad_[n];

    float m = -1e30f;
    for (int i = beg + lane; i < end; i += 32)
        m = fmaxf(m, lrelu(as_[g_csr[i]] + adn));
#pragma unroll
    for (int o = 16; o; o >>= 1) m = fmaxf(m, __shfl_xor_sync(0xffffffffu, m, o));

    float ws = 0.f;
    float4 acc = make_float4(0.f, 0.f, 0.f, 0.f);
    const float4* h4 = (const float4*)hpre;
    for (int i = beg; i < end; i++) {
        int s = g_csr[i];
        float ex = __expf(lrelu(as_[s] + adn) - m);
        ws += ex;
        float4 v = h4[(size_t)s * 32 + lane];
        acc.x += ex * v.x; acc.y += ex * v.y; acc.z += ex * v.z; acc.w += ex * v.w;
    }
    float inv = 1.f / (ws + 1e-16f);
    float bt = *beta;
    float4 b = ((const float4*)bias)[lane];
    float4 gv = ((const float4*)gp)[(size_t)n * 32 + lane];
    float4 o;
    o.x = acc.x * inv + b.x + bt * gv.x;
    o.y = acc.y * inv + b.y + bt * gv.y;
    o.z = acc.z * inv + b.z + bt * gv.z;
    o.w = acc.w * inv + b.w + bt * gv.w;
    size_t oi = (size_t)n * 128 + lane * 4;
    __nv_bfloat162 h01, h23, l01, l23;
    h01.x = __float2bfloat16(o.x); l01.x = __float2bfloat16(o.x - __bfloat162float(h01.x));
    h01.y = __float2bfloat16(o.y); l01.y = __float2bfloat16(o.y - __bfloat162float(h01.y));
    h23.x = __float2bfloat16(o.z); l23.x = __float2bfloat16(o.z - __bfloat162float(h23.x));
    h23.y = __float2bfloat16(o.w); l23.y = __float2bfloat16(o.w - __bfloat162float(h23.y));
    *(__nv_bfloat162*)(ohi + oi) = h01; *(__nv_bfloat162*)(ohi + oi + 2) = h23;
    *(__nv_bfloat162*)(olo + oi) = l01; *(__nv_bfloat162*)(olo + oi + 2) = l23;
}

// ---------------- launch ----------------
extern "C" void kernel_launch(void* const* d_in, const int* in_sizes, int n_in,
                              void* d_out, int out_size) {
    const float* x      = (const float*)d_in[0];
    const int*   ei     = (const int*)  d_in[1];
    const float* g      = (const float*)d_in[2];
    const float* proj_W = (const float*)d_in[3];
    const float* proj_b = (const float*)d_in[4];
    const float* g1_W   = (const float*)d_in[5];
    const float* g1_as  = (const float*)d_in[6];
    const float* g1_ad  = (const float*)d_in[7];
    const float* g1_b   = (const float*)d_in[8];
    const float* g2_W   = (const float*)d_in[9];
    const float* g2_as  = (const float*)d_in[10];
    const float* g2_ad  = (const float*)d_in[11];
    const float* g2_b   = (const float*)d_in[12];
    const float* dec_W  = (const float*)d_in[13];
    const float* dec_b  = (const float*)d_in[14];
    const float* beta   = (const float*)d_in[15];
    float* out = (float*)d_out;

    __nv_bfloat16 *xg_hi, *xg_lo, *xpgp_hi, *xpgp_lo, *h1_hi, *h1_lo, *h2_hi, *h2_lo;
    __nv_bfloat16 *wp_hi, *wp_lo, *w1_hi, *w1_lo, *w2_hi, *w2_lo, *wd_hi, *wd_lo;
    float *xpgp, *h1pre, *h2pre, *as1, *ad1, *as2, *ad2;
    cudaGetSymbolAddress((void**)&xg_hi,   g_xg_hi);   cudaGetSymbolAddress((void**)&xg_lo,   g_xg_lo);
    cudaGetSymbolAddress((void**)&xpgp,    g_xpgp);
    cudaGetSymbolAddress((void**)&xpgp_hi, g_xpgp_hi); cudaGetSymbolAddress((void**)&xpgp_lo, g_xpgp_lo);
    cudaGetSymbolAddress((void**)&h1pre,   g_h1pre);
    cudaGetSymbolAddress((void**)&h1_hi,   g_h1_hi);   cudaGetSymbolAddress((void**)&h1_lo,   g_h1_lo);
    cudaGetSymbolAddress((void**)&h2pre,   g_h2pre);
    cudaGetSymbolAddress((void**)&h2_hi,   g_h2_hi);   cudaGetSymbolAddress((void**)&h2_lo,   g_h2_lo);
    cudaGetSymbolAddress((void**)&wp_hi,   g_wp_hi);   cudaGetSymbolAddress((void**)&wp_lo,   g_wp_lo);
    cudaGetSymbolAddress((void**)&w1_hi,   g_w1_hi);   cudaGetSymbolAddress((void**)&w1_lo,   g_w1_lo);
    cudaGetSymbolAddress((void**)&w2_hi,   g_w2_hi);   cudaGetSymbolAddress((void**)&w2_lo,   g_w2_lo);
    cudaGetSymbolAddress((void**)&wd_hi,   g_wd_hi);   cudaGetSymbolAddress((void**)&wd_lo,   g_wd_lo);
    cudaGetSymbolAddress((void**)&as1, g_as1); cudaGetSymbolAddress((void**)&ad1, g_ad1);
    cudaGetSymbolAddress((void**)&as2, g_as2); cudaGetSymbolAddress((void**)&ad2, g_ad2);

    cudaFuncSetAttribute(k_gemm_mma<4>, cudaFuncAttributeMaxDynamicSharedMemorySize, GSMEM4);
    cudaFuncSetAttribute(k_gemm_mma<2>, cudaFuncAttributeMaxDynamicSharedMemorySize, GSMEM2);

    // CSR
    k_zero_deg<<<(NN + 255) / 256, 256>>>();
    k_count<<<(EE + 255) / 256, 256>>>(ei);
    k_scan<<<1, 1024>>>();
    k_fill<<<(TE + 255) / 256, 256>>>(ei);

    // input splits
    {
        int n4 = NN * DIN / 4;
        k_split<<<(n4 + 255) / 256, 256>>>(x, xg_hi, xg_lo, n4);
        k_split<<<(n4 + 255) / 256, 256>>>(g, xg_hi + (size_t)NN * DIN, xg_lo + (size_t)NN * DIN, n4);
    }
    // weight transpose + split
    k_wsplit<<<(DIN * DH + 255) / 256, 256>>>(proj_W, wp_hi, wp_lo, DIN, DH);
    k_wsplit<<<(DH * HEADS * DH + 255) / 256, 256>>>(g1_W, w1_hi, w1_lo, DH, HEADS * DH);
    k_wsplit<<<(HEADS * DH * DH + 255) / 256, 256>>>(g2_W, w2_hi, w2_lo, HEADS * DH, DH);
    k_wsplit<<<(DH * DIN + 255) / 256, 256>>>(dec_W, wd_hi, wd_lo, DH, DIN);

    // proj (batched x|g): [20000,768] @ [768,128]
    k_gemm_mma<4><<<dim3(1, (MP + 127) / 128), 256, GSMEM4>>>(
        xg_hi, xg_lo, wp_hi, wp_lo, proj_b, xpgp, xpgp_hi, xpgp_lo, MP, DIN, DH);

    // GAT1: [10000,128] @ [128,512]
    k_gemm_mma<4><<<dim3(HEADS * DH / 128, (NN + 127) / 128), 256, GSMEM4>>>(
        xpgp_hi, xpgp_lo, w1_hi, w1_lo, nullptr, h1pre, nullptr, nullptr, NN, DH, HEADS * DH);
    k_attdot<<<(NN * HEADS * 32 + 255) / 256, 256>>>(h1pre, g1_as, g1_ad, as1, ad1, HEADS);
    k_agg1<<<(NN * HEADS * 32 + 255) / 256, 256>>>(h1pre, as1, ad1, g1_b, h1_hi, h1_lo);

    // GAT2: [10000,512] @ [512,128]  (BM=64 -> 157 CTAs, full-chip)
    k_gemm_mma<2><<<dim3(1, (NN + 63) / 64), 256, GSMEM2>>>(
        h1_hi, h1_lo, w2_hi, w2_lo, nullptr, h2pre, nullptr, nullptr, NN, HEADS * DH, DH);
    k_attdot<<<(NN * 32 + 255) / 256, 256>>>(h2pre, g2_as, g2_ad, as2, ad2, 1);
    k_agg2<<<(NN * 32 + 255) / 256, 256>>>(h2pre, as2, ad2, g2_b, xpgp + (size_t)NN * DH, beta, h2_hi, h2_lo);

    // decoder: [10000,128] @ [128,768]
    k_gemm_mma<4><<<dim3(DIN / 128, (NN + 127) / 128), 256, GSMEM4>>>(
        h2_hi, h2_lo, wd_hi, wd_lo, dec_b, out, nullptr, nullptr, NN, DH, DIN);
}

// round 7
// speedup vs baseline: 2.6288x; 1.1613x over previous
#include <cuda_runtime.h>
#include <cuda_bf16.h>
#include <cstdint>

#define NN    10000
#define EE    160000
#define TE    (EE + NN)
#define DIN   768
#define DH    128
#define HEADS 4
#define MP    (2 * NN)           // batched proj rows (x then g)

// ---------------- scratch (static device globals) ----------------
__device__ __align__(256) __nv_bfloat16 g_xg_hi[MP * DIN], g_xg_lo[MP * DIN];
__device__ __align__(256) float         g_xpgp[MP * DH];
__device__ __align__(256) __nv_bfloat16 g_xpgp_hi[MP * DH], g_xpgp_lo[MP * DH];
__device__ __align__(256) float         g_h1pre[NN * HEADS * DH];
__device__ __align__(256) __nv_bfloat16 g_h1_hi[NN * HEADS * DH], g_h1_lo[NN * HEADS * DH];
__device__ __align__(256) float         g_h2pre[NN * DH];
__device__ __align__(256) __nv_bfloat16 g_h2_hi[NN * DH], g_h2_lo[NN * DH];
// transposed + split weights: Bt[n][k]
__device__ __align__(256) __nv_bfloat16 g_wp_hi[DH * DIN],        g_wp_lo[DH * DIN];
__device__ __align__(256) __nv_bfloat16 g_w1_hi[HEADS * DH * DH], g_w1_lo[HEADS * DH * DH];
__device__ __align__(256) __nv_bfloat16 g_w2_hi[DH * HEADS * DH], g_w2_lo[DH * HEADS * DH];
__device__ __align__(256) __nv_bfloat16 g_wd_hi[DIN * DH],        g_wd_lo[DIN * DH];
__device__ float g_as1[NN * HEADS], g_ad1[NN * HEADS], g_as2[NN], g_ad2[NN];
__device__ int   g_deg[NN], g_off[NN + 1], g_cur[NN], g_csr[TE];

// ---------------- helpers ----------------
__device__ __forceinline__ uint32_t smem_u32(const void* p) {
    uint32_t a;
    asm("{ .reg .u64 t; cvta.to.shared.u64 t, %1; cvt.u32.u64 %0, t; }" : "=r"(a) : "l"(p));
    return a;
}
__device__ __forceinline__ void cp16(uint32_t dst, const void* src) {
    asm volatile("cp.async.cg.shared.global [%0], [%1], 16;" :: "r"(dst), "l"(src));
}
#define CP_COMMIT() asm volatile("cp.async.commit_group;" ::: "memory")
#define CP_WAIT1()  asm volatile("cp.async.wait_group 1;" ::: "memory")
#define CP_WAIT0()  asm volatile("cp.async.wait_group 0;" ::: "memory")

__device__ __forceinline__ void mma_bf16(float* c, uint32_t a0, uint32_t a1, uint32_t a2, uint32_t a3,
                                         uint32_t b0, uint32_t b1) {
    asm volatile("mma.sync.aligned.m16n8k16.row.col.f32.bf16.bf16.f32 "
                 "{%0,%1,%2,%3}, {%4,%5,%6,%7}, {%8,%9}, {%0,%1,%2,%3};"
                 : "+f"(c[0]), "+f"(c[1]), "+f"(c[2]), "+f"(c[3])
                 : "r"(a0), "r"(a1), "r"(a2), "r"(a3), "r"(b0), "r"(b1));
}
__device__ __forceinline__ void ldsm4(uint32_t* r, uint32_t addr) {
    asm volatile("ldmatrix.sync.aligned.m8n8.x4.shared.b16 {%0,%1,%2,%3}, [%4];"
                 : "=r"(r[0]), "=r"(r[1]), "=r"(r[2]), "=r"(r[3]) : "r"(addr));
}

// ---------------- CSR build ----------------
__global__ void k_count(const int* __restrict__ ei) {
    int i = blockIdx.x * blockDim.x + threadIdx.x;
    if (i < EE) atomicAdd(&g_deg[ei[EE + i]], 1);
}
__global__ void k_scan() {
    __shared__ int sh[1024];
    const int CH = 10;
    int tid = threadIdx.x, base = tid * CH, s = 0;
#pragma unroll
    for (int j = 0; j < CH; j++) { int idx = base + j; if (idx < NN) s += g_deg[idx] + 1; }
    sh[tid] = s;
    __syncthreads();
    for (int o = 1; o < 1024; o <<= 1) {
        int t = (tid >= o) ? sh[tid - o] : 0;
        __syncthreads();
        sh[tid] += t;
        __syncthreads();
    }
    int run = sh[tid] - s;
#pragma unroll
    for (int j = 0; j < CH; j++) {
        int idx = base + j;
        if (idx < NN) { g_off[idx] = run; g_cur[idx] = run; run += g_deg[idx] + 1; }
    }
    if (tid == 0) g_off[NN] = sh[1023];
}
__global__ void k_fill(const int* __restrict__ ei) {
    int i = blockIdx.x * blockDim.x + threadIdx.x;
    if (i < EE) {
        int d = ei[EE + i];
        g_csr[atomicAdd(&g_cur[d], 1)] = ei[i];
    } else if (i < TE) {
        int n = i - EE;
        g_csr[atomicAdd(&g_cur[n], 1)] = n;
    }
}

// ---------------- fused input split (x rows [0,NN), g rows [NN,2NN)) + deg zero ----------------
__device__ __forceinline__ void split4(const float4 v, __nv_bfloat16* hi, __nv_bfloat16* lo, size_t i4) {
    __nv_bfloat162 h01, h23, l01, l23;
    h01.x = __float2bfloat16(v.x); l01.x = __float2bfloat16(v.x - __bfloat162float(h01.x));
    h01.y = __float2bfloat16(v.y); l01.y = __float2bfloat16(v.y - __bfloat162float(h01.y));
    h23.x = __float2bfloat16(v.z); l23.x = __float2bfloat16(v.z - __bfloat162float(h23.x));
    h23.y = __float2bfloat16(v.w); l23.y = __float2bfloat16(v.w - __bfloat162float(h23.y));
    ((__nv_bfloat162*)hi)[i4 * 2] = h01; ((__nv_bfloat162*)hi)[i4 * 2 + 1] = h23;
    ((__nv_bfloat162*)lo)[i4 * 2] = l01; ((__nv_bfloat162*)lo)[i4 * 2 + 1] = l23;
}

#define N4 (NN * DIN / 4)
__global__ void k_splitall(const float* __restrict__ x, const float* __restrict__ g,
                           __nv_bfloat16* __restrict__ hi, __nv_bfloat16* __restrict__ lo) {
    int i = blockIdx.x * blockDim.x + threadIdx.x;
    if (i < NN) g_deg[i] = 0;
    if (i < N4) {
        split4(((const float4*)x)[i], hi, lo, i);
    } else if (i < 2 * N4) {
        int j = i - N4;
        split4(((const float4*)g)[j], hi + (size_t)NN * DIN, lo + (size_t)NN * DIN, j);
    }
}

// ---------------- fused weight transpose+split for all 4 weights ----------------
#define WS1 (DIN * DH)
#define WS2 (DH * HEADS * DH)
#define WS3 (HEADS * DH * DH)
#define WS4 (DH * DIN)
__global__ void k_wsplitall(const float* __restrict__ Wp, const float* __restrict__ W1,
                            const float* __restrict__ W2, const float* __restrict__ Wd,
                            __nv_bfloat16* __restrict__ wph, __nv_bfloat16* __restrict__ wpl,
                            __nv_bfloat16* __restrict__ w1h, __nv_bfloat16* __restrict__ w1l,
                            __nv_bfloat16* __restrict__ w2h, __nv_bfloat16* __restrict__ w2l,
                            __nv_bfloat16* __restrict__ wdh, __nv_bfloat16* __restrict__ wdl) {
    int i = blockIdx.x * blockDim.x + threadIdx.x;
    const float* W; __nv_bfloat16 *bh, *bl; int K, N, j;
    if (i < WS1)                         { W = Wp; bh = wph; bl = wpl; K = DIN; N = DH;         j = i; }
    else if (i < WS1 + WS2)              { W = W1; bh = w1h; bl = w1l; K = DH;  N = HEADS * DH; j = i - WS1; }
    else if (i < WS1 + WS2 + WS3)        { W = W2; bh = w2h; bl = w2l; K = HEADS * DH; N = DH;  j = i - WS1 - WS2; }
    else if (i < WS1 + WS2 + WS3 + WS4)  { W = Wd; bh = wdh; bl = wdl; K = DH;  N = DIN;        j = i - WS1 - WS2 - WS3; }
    else return;
    int k = j / N, n = j - k * N;
    float v = W[j];
    __nv_bfloat16 h = __float2bfloat16(v);
    bh[(size_t)n * K + k] = h;
    bl[(size_t)n * K + k] = __float2bfloat16(v - __bfloat162float(h));
}

// ---------------- mma.sync bf16x3 GEMM (BM=64, occ 2) with fused attention dots ----------------
#define RS_B   80
#define B_B    10240
#define BM     64
#define A_B    (BM * RS_B)
#define STG    (2 * A_B + 2 * B_B)
#define GSMEM  (2 * STG)          // 61440

__global__ __launch_bounds__(256, 2) void k_gemm_mma(
    const __nv_bfloat16* __restrict__ Ahi, const __nv_bfloat16* __restrict__ Alo,
    const __nv_bfloat16* __restrict__ Bhi, const __nv_bfloat16* __restrict__ Blo,
    const float* __restrict__ bias,
    float* __restrict__ Cf, __nv_bfloat16* __restrict__ Chi, __nv_bfloat16* __restrict__ Clo,
    const float* __restrict__ attS, const float* __restrict__ attD,
    float* __restrict__ outS, float* __restrict__ outD,
    int M, int K, int Nc)
{
    constexpr int MT = 2;
    extern __shared__ char smem[];
    const uint32_t sb = smem_u32(smem);
    const int tid = threadIdx.x, wid = tid >> 5, lane = tid & 31;
    const int gid = lane >> 2, tig = lane & 3;
    const int mBase = blockIdx.y * BM, nBase = blockIdx.x * 128;
    const int wrow = (wid & 1) * 32, wcol = (wid >> 1) * 32;

    float acc[MT][4][4];
#pragma unroll
    for (int i = 0; i < MT; i++)
#pragma unroll
        for (int j = 0; j < 4; j++)
#pragma unroll
            for (int q = 0; q < 4; q++) acc[i][j][q] = 0.f;

    const int nchunk = K >> 5;
    const uint32_t aOff = (uint32_t)((wrow + (lane & 15)) * RS_B + (lane >> 4) * 16);
    const uint32_t bOff = (uint32_t)(2 * A_B + (wcol + ((lane >> 4) << 3) + (lane & 7)) * RS_B
                                     + ((lane >> 3) & 1) * 16);

    auto fill = [&](uint32_t bufbase, int k0) {
        {   // A: 4*BM = 256 chunks, 1 per thread
            int row = tid >> 2, seg = tid & 3;
            uint32_t so = (uint32_t)(row * RS_B + seg * 16);
            int ra = mBase + row; if (ra > M - 1) ra = M - 1;
            size_t ea = (size_t)ra * K + k0 + seg * 8;
            cp16(bufbase + so,       Ahi + ea);
            cp16(bufbase + A_B + so, Alo + ea);
        }
#pragma unroll
        for (int i = tid; i < 512; i += 256) {
            int row = i >> 2, seg = i & 3;
            uint32_t so = (uint32_t)(row * RS_B + seg * 16);
            size_t eb = (size_t)(nBase + row) * K + k0 + seg * 8;
            cp16(bufbase + 2 * A_B + so,       Bhi + eb);
            cp16(bufbase + 2 * A_B + B_B + so, Blo + eb);
        }
    };

    fill(sb, 0);
    CP_COMMIT();

    for (int c = 0; c < nchunk; c++) {
        if (c + 1 < nchunk) {
            fill(sb + ((c + 1) & 1) * STG, (c + 1) << 5);
            CP_COMMIT();
            CP_WAIT1();
        } else {
            CP_WAIT0();
        }
        __syncthreads();

        const uint32_t sbuf = sb + (c & 1) * STG;
        const uint32_t aB = sbuf + aOff;
        const uint32_t bB = sbuf + bOff;

#pragma unroll
        for (int ks = 0; ks < 2; ks++) {
            const uint32_t ko = ks * 32;
            uint32_t ah[MT][4], al[MT][4], bh[4][2], bl[4][2];
#pragma unroll
            for (int mt = 0; mt < MT; mt++) {
                ldsm4(ah[mt], aB + mt * (16 * RS_B) + ko);
                ldsm4(al[mt], aB + A_B + mt * (16 * RS_B) + ko);
            }
#pragma unroll
            for (int p = 0; p < 2; p++) {
                uint32_t r[4];
                ldsm4(r, bB + p * (16 * RS_B) + ko);
                bh[2 * p][0] = r[0]; bh[2 * p][1] = r[1];
                bh[2 * p + 1][0] = r[2]; bh[2 * p + 1][1] = r[3];
                ldsm4(r, bB + B_B + p * (16 * RS_B) + ko);
                bl[2 * p][0] = r[0]; bl[2 * p][1] = r[1];
                bl[2 * p + 1][0] = r[2]; bl[2 * p + 1][1] = r[3];
            }
#pragma unroll
            for (int mt = 0; mt < MT; mt++)
#pragma unroll
                for (int nt = 0; nt < 4; nt++) {
                    mma_bf16(acc[mt][nt], ah[mt][0], ah[mt][1], ah[mt][2], ah[mt][3], bh[nt][0], bh[nt][1]);
                    mma_bf16(acc[mt][nt], ah[mt][0], ah[mt][1], ah[mt][2], ah[mt][3], bl[nt][0], bl[nt][1]);
                    mma_bf16(acc[mt][nt], al[mt][0], al[mt][1], al[mt][2], al[mt][3], bh[nt][0], bh[nt][1]);
                }
        }
        __syncthreads();
    }

    // epilogue (+ optional fused attention dot partials)
    float* sA = (float*)smem;            // [4][BM] per column-group warp pair
    float* sD = sA + 4 * BM;
    const int hh = blockIdx.x;           // head index when attS != null (Nc = H*128)

#pragma unroll
    for (int mt = 0; mt < MT; mt++) {
#pragma unroll
        for (int half = 0; half < 2; half++) {
            const int lrow = wrow + mt * 16 + gid + half * 8;
            const int row = mBase + lrow;
            float ps = 0.f, pd = 0.f;
#pragma unroll
            for (int nt = 0; nt < 4; nt++) {
                const int cl = wcol + nt * 8 + tig * 2;
                const int col = nBase + cl;
                float v0 = acc[mt][nt][half * 2 + 0];
                float v1 = acc[mt][nt][half * 2 + 1];
                if (bias) { v0 += bias[col]; v1 += bias[col + 1]; }
                if (attS) {
                    ps += v0 * attS[hh * 128 + cl] + v1 * attS[hh * 128 + cl + 1];
                    pd += v0 * attD[hh * 128 + cl] + v1 * attD[hh * 128 + cl + 1];
                }
                if (row < M) {
                    size_t oi = (size_t)row * Nc + col;
                    if (Cf) *(float2*)(Cf + oi) = make_float2(v0, v1);
                    if (Chi) {
                        __nv_bfloat162 h, l;
                        h.x = __float2bfloat16(v0); l.x = __float2bfloat16(v0 - __bfloat162float(h.x));
                        h.y = __float2bfloat16(v1); l.y = __float2bfloat16(v1 - __bfloat162float(h.y));
                        *(__nv_bfloat162*)(Chi + oi) = h;
                        *(__nv_bfloat162*)(Clo + oi) = l;
                    }
                }
            }
            if (attS) {
                ps += __shfl_xor_sync(0xffffffffu, ps, 1);
                ps += __shfl_xor_sync(0xffffffffu, ps, 2);
                pd += __shfl_xor_sync(0xffffffffu, pd, 1);
                pd += __shfl_xor_sync(0xffffffffu, pd, 2);
                if (tig == 0) {
                    sA[(wid >> 1) * BM + lrow] = ps;
                    sD[(wid >> 1) * BM + lrow] = pd;
                }
            }
        }
    }
    if (attS) {
        __syncthreads();
        if (tid < BM) {
            int row = mBase + tid;
            if (row < M) {
                int H = Nc >> 7;
                outS[row * H + hh] = sA[tid] + sA[BM + tid] + sA[2 * BM + tid] + sA[3 * BM + tid];
                outD[row * H + hh] = sD[tid] + sD[BM + tid] + sD[2 * BM + tid] + sD[3 * BM + tid];
            }
        }
    }
}

__device__ __forceinline__ float lrelu(float e) { return e > 0.f ? e : 0.2f * e; }

// ---------------- GAT1 agg: bias + ELU + bf16 split out ----------------
__global__ void k_agg1(const float* __restrict__ hpre, const float* __restrict__ as_,
                       const float* __restrict__ ad_, const float* __restrict__ bias,
                       __nv_bfloat16* __restrict__ ohi, __nv_bfloat16* __restrict__ olo) {
    int gw = (blockIdx.x * blockDim.x + threadIdx.x) >> 5;
    int lane = threadIdx.x & 31;
    if (gw >= NN * HEADS) return;
    int n = gw / HEADS, hh = gw - n * HEADS;
    int beg = g_off[n], end = g_off[n + 1];
    float adn = ad_[gw];

    float m = -1e30f;
    for (int i = beg + lane; i < end; i += 32)
        m = fmaxf(m, lrelu(as_[g_csr[i] * HEADS + hh] + adn));
#pragma unroll
    for (int o = 16; o; o >>= 1) m = fmaxf(m, __shfl_xor_sync(0xffffffffu, m, o));

    float ws = 0.f;
    float4 acc = make_float4(0.f, 0.f, 0.f, 0.f);
    const float4* h4 = (const float4*)hpre;
    for (int i = beg; i < end; i++) {
        int s = g_csr[i];
        float ex = __expf(lrelu(as_[s * HEADS + hh] + adn) - m);
        ws += ex;
        float4 v = h4[(size_t)(s * HEADS + hh) * 32 + lane];
        acc.x += ex * v.x; acc.y += ex * v.y; acc.z += ex * v.z; acc.w += ex * v.w;
    }
    float inv = 1.f / (ws + 1e-16f);
    float4 b = ((const float4*)bias)[hh * 32 + lane];
    float4 o;
    o.x = acc.x * inv + b.x; o.y = acc.y * inv + b.y;
    o.z = acc.z * inv + b.z; o.w = acc.w * inv + b.w;
    o.x = o.x > 0.f ? o.x : expm1f(o.x);
    o.y = o.y > 0.f ? o.y : expm1f(o.y);
    o.z = o.z > 0.f ? o.z : expm1f(o.z);
    o.w = o.w > 0.f ? o.w : expm1f(o.w);
    size_t oi = (size_t)gw * 128 + lane * 4;
    __nv_bfloat162 h01, h23, l01, l23;
    h01.x = __float2bfloat16(o.x); l01.x = __float2bfloat16(o.x - __bfloat162float(h01.x));
    h01.y = __float2bfloat16(o.y); l01.y = __float2bfloat16(o.y - __bfloat162float(h01.y));
    h23.x = __float2bfloat16(o.z); l23.x = __float2bfloat16(o.z - __bfloat162float(h23.x));
    h23.y = __float2bfloat16(o.w); l23.y = __float2bfloat16(o.w - __bfloat162float(h23.y));
    *(__nv_bfloat162*)(ohi + oi) = h01; *(__nv_bfloat162*)(ohi + oi + 2) = h23;
    *(__nv_bfloat162*)(olo + oi) = l01; *(__nv_bfloat162*)(olo + oi + 2) = l23;
}

// ---------------- GAT2 agg: bias + beta*gp + bf16 split out ----------------
__global__ void k_agg2(const float* __restrict__ hpre, const float* __restrict__ as_,
                       const float* __restrict__ ad_, const float* __restrict__ bias,
                       const float* __restrict__ gp, const float* __restrict__ beta,
                       __nv_bfloat16* __restrict__ ohi, __nv_bfloat16* __restrict__ olo) {
    int n = (blockIdx.x * blockDim.x + threadIdx.x) >> 5;
    int lane = threadIdx.x & 31;
    if (n >= NN) return;
    int beg = g_off[n], end = g_off[n + 1];
    float adn = ad_[n];

    float m = -1e30f;
    for (int i = beg + lane; i < end; i += 32)
        m = fmaxf(m, lrelu(as_[g_csr[i]] + adn));
#pragma unroll
    for (int o = 16; o; o >>= 1) m = fmaxf(m, __shfl_xor_sync(0xffffffffu, m, o));

    float ws = 0.f;
    float4 acc = make_float4(0.f, 0.f, 0.f, 0.f);
    const float4* h4 = (const float4*)hpre;
    for (int i = beg; i < end; i++) {
        int s = g_csr[i];
        float ex = __expf(lrelu(as_[s] + adn) - m);
        ws += ex;
        float4 v = h4[(size_t)s * 32 + lane];
        acc.x += ex * v.x; acc.y += ex * v.y; acc.z += ex * v.z; acc.w += ex * v.w;
    }
    float inv = 1.f / (ws + 1e-16f);
    float bt = *beta;
    float4 b = ((const float4*)bias)[lane];
    float4 gv = ((const float4*)gp)[(size_t)n * 32 + lane];
    float4 o;
    o.x = acc.x * inv + b.x + bt * gv.x;
    o.y = acc.y * inv + b.y + bt * gv.y;
    o.z = acc.z * inv + b.z + bt * gv.z;
    o.w = acc.w * inv + b.w + bt * gv.w;
    size_t oi = (size_t)n * 128 + lane * 4;
    __nv_bfloat162 h01, h23, l01, l23;
    h01.x = __float2bfloat16(o.x); l01.x = __float2bfloat16(o.x - __bfloat162float(h01.x));
    h01.y = __float2bfloat16(o.y); l01.y = __float2bfloat16(o.y - __bfloat162float(h01.y));
    h23.x = __float2bfloat16(o.z); l23.x = __float2bfloat16(o.z - __bfloat162float(h23.x));
    h23.y = __float2bfloat16(o.w); l23.y = __float2bfloat16(o.w - __bfloat162float(h23.y));
    *(__nv_bfloat162*)(ohi + oi) = h01; *(__nv_bfloat162*)(ohi + oi + 2) = h23;
    *(__nv_bfloat162*)(olo + oi) = l01; *(__nv_bfloat162*)(olo + oi + 2) = l23;
}

// ---------------- launch ----------------
extern "C" void kernel_launch(void* const* d_in, const int* in_sizes, int n_in,
                              void* d_out, int out_size) {
    const float* x      = (const float*)d_in[0];
    const int*   ei     = (const int*)  d_in[1];
    const float* g      = (const float*)d_in[2];
    const float* proj_W = (const float*)d_in[3];
    const float* proj_b = (const float*)d_in[4];
    const float* g1_W   = (const float*)d_in[5];
    const float* g1_as  = (const float*)d_in[6];
    const float* g1_ad  = (const float*)d_in[7];
    const float* g1_b   = (const float*)d_in[8];
    const float* g2_W   = (const float*)d_in[9];
    const float* g2_as  = (const float*)d_in[10];
    const float* g2_ad  = (const float*)d_in[11];
    const float* g2_b   = (const float*)d_in[12];
    const float* dec_W  = (const float*)d_in[13];
    const float* dec_b  = (const float*)d_in[14];
    const float* beta   = (const float*)d_in[15];
    float* out = (float*)d_out;

    __nv_bfloat16 *xg_hi, *xg_lo, *xpgp_hi, *xpgp_lo, *h1_hi, *h1_lo, *h2_hi, *h2_lo;
    __nv_bfloat16 *wp_hi, *wp_lo, *w1_hi, *w1_lo, *w2_hi, *w2_lo, *wd_hi, *wd_lo;
    float *xpgp, *h1pre, *h2pre, *as1, *ad1, *as2, *ad2;
    cudaGetSymbolAddress((void**)&xg_hi,   g_xg_hi);   cudaGetSymbolAddress((void**)&xg_lo,   g_xg_lo);
    cudaGetSymbolAddress((void**)&xpgp,    g_xpgp);
    cudaGetSymbolAddress((void**)&xpgp_hi, g_xpgp_hi); cudaGetSymbolAddress((void**)&xpgp_lo, g_xpgp_lo);
    cudaGetSymbolAddress((void**)&h1pre,   g_h1pre);
    cudaGetSymbolAddress((void**)&h1_hi,   g_h1_hi);   cudaGetSymbolAddress((void**)&h1_lo,   g_h1_lo);
    cudaGetSymbolAddress((void**)&h2pre,   g_h2pre);
    cudaGetSymbolAddress((void**)&h2_hi,   g_h2_hi);   cudaGetSymbolAddress((void**)&h2_lo,   g_h2_lo);
    cudaGetSymbolAddress((void**)&wp_hi,   g_wp_hi);   cudaGetSymbolAddress((void**)&wp_lo,   g_wp_lo);
    cudaGetSymbolAddress((void**)&w1_hi,   g_w1_hi);   cudaGetSymbolAddress((void**)&w1_lo,   g_w1_lo);
    cudaGetSymbolAddress((void**)&w2_hi,   g_w2_hi);   cudaGetSymbolAddress((void**)&w2_lo,   g_w2_lo);
    cudaGetSymbolAddress((void**)&wd_hi,   g_wd_hi);   cudaGetSymbolAddress((void**)&wd_lo,   g_wd_lo);
    cudaGetSymbolAddress((void**)&as1, g_as1); cudaGetSymbolAddress((void**)&ad1, g_ad1);
    cudaGetSymbolAddress((void**)&as2, g_as2); cudaGetSymbolAddress((void**)&ad2, g_ad2);

    cudaFuncSetAttribute(k_gemm_mma, cudaFuncAttributeMaxDynamicSharedMemorySize, GSMEM);

    // fused input split (+ deg zero), fused weight split
    k_splitall<<<(2 * N4 + 255) / 256, 256>>>(x, g, xg_hi, xg_lo);
    k_wsplitall<<<(WS1 + WS2 + WS3 + WS4 + 255) / 256, 256>>>(
        proj_W, g1_W, g2_W, dec_W, wp_hi, wp_lo, w1_hi, w1_lo, w2_hi, w2_lo, wd_hi, wd_lo);

    // CSR (deg already zeroed by k_splitall)
    k_count<<<(EE + 255) / 256, 256>>>(ei);
    k_scan<<<1, 1024>>>();
    k_fill<<<(TE + 255) / 256, 256>>>(ei);

    // proj (batched x|g): [20000,768] @ [768,128]
    k_gemm_mma<<<dim3(1, (MP + BM - 1) / BM), 256, GSMEM>>>(
        xg_hi, xg_lo, wp_hi, wp_lo, proj_b, xpgp, xpgp_hi, xpgp_lo,
        nullptr, nullptr, nullptr, nullptr, MP, DIN, DH);

    // GAT1: [10000,128] @ [128,512]  + fused attention dots
    k_gemm_mma<<<dim3(HEADS * DH / 128, (NN + BM - 1) / BM), 256, GSMEM>>>(
        xpgp_hi, xpgp_lo, w1_hi, w1_lo, nullptr, h1pre, nullptr, nullptr,
        g1_as, g1_ad, as1, ad1, NN, DH, HEADS * DH);
    k_agg1<<<(NN * HEADS * 32 + 255) / 256, 256>>>(h1pre, as1, ad1, g1_b, h1_hi, h1_lo);

    // GAT2: [10000,512] @ [512,128]  + fused attention dots
    k_gemm_mma<<<dim3(1, (NN + BM - 1) / BM), 256, GSMEM>>>(
        h1_hi, h1_lo, w2_hi, w2_lo, nullptr, h2pre, nullptr, nullptr,
        g2_as, g2_ad, as2, ad2, NN, HEADS * DH, DH);
    k_agg2<<<(NN * 32 + 255) / 256, 256>>>(h2pre, as2, ad2, g2_b, xpgp + (size_t)NN * DH, beta, h2_hi, h2_lo);

    // decoder: [10000,128] @ [128,768]
    k_gemm_mma<<<dim3(DIN / 128, (NN + BM - 1) / BM), 256, GSMEM>>>(
        h2_hi, h2_lo, wd_hi, wd_lo, dec_b, out, nullptr, nullptr,
        nullptr, nullptr, nullptr, nullptr, NN, DH, DIN);
}

// round 8
// speedup vs baseline: 2.7861x; 1.0598x over previous
#include <cuda_runtime.h>
#include <cuda_bf16.h>
#include <cstdint>

#define NN    10000
#define EE    160000
#define TE    (EE + NN)
#define DIN   768
#define DH    128
#define HEADS 4
#define MP    (2 * NN)           // batched proj rows (x then g)

// ---------------- scratch (static device globals) ----------------
__device__ __align__(256) __nv_bfloat16 g_xg_hi[MP * DIN], g_xg_lo[MP * DIN];
__device__ __align__(256) float         g_xpgp[MP * DH];
__device__ __align__(256) __nv_bfloat16 g_xpgp_hi[MP * DH], g_xpgp_lo[MP * DH];
__device__ __align__(256) float         g_h1pre[NN * HEADS * DH];
__device__ __align__(256) __nv_bfloat16 g_h1_hi[NN * HEADS * DH], g_h1_lo[NN * HEADS * DH];
__device__ __align__(256) float         g_h2pre[NN * DH];
__device__ __align__(256) __nv_bfloat16 g_h2_hi[NN * DH], g_h2_lo[NN * DH];
// transposed + split weights: Bt[n][k]
__device__ __align__(256) __nv_bfloat16 g_wp_hi[DH * DIN],        g_wp_lo[DH * DIN];
__device__ __align__(256) __nv_bfloat16 g_w1_hi[HEADS * DH * DH], g_w1_lo[HEADS * DH * DH];
__device__ __align__(256) __nv_bfloat16 g_w2_hi[DH * HEADS * DH], g_w2_lo[DH * HEADS * DH];
__device__ __align__(256) __nv_bfloat16 g_wd_hi[DIN * DH],        g_wd_lo[DIN * DH];
__device__ float g_as1[NN * HEADS], g_ad1[NN * HEADS], g_as2[NN], g_ad2[NN];
__device__ int   g_deg[NN], g_off[NN + 1], g_cur[NN], g_csr[TE];

// ---------------- helpers ----------------
__device__ __forceinline__ uint32_t smem_u32(const void* p) {
    uint32_t a;
    asm("{ .reg .u64 t; cvta.to.shared.u64 t, %1; cvt.u32.u64 %0, t; }" : "=r"(a) : "l"(p));
    return a;
}
__device__ __forceinline__ void cp16(uint32_t dst, const void* src) {
    asm volatile("cp.async.cg.shared.global [%0], [%1], 16;" :: "r"(dst), "l"(src));
}
#define CP_COMMIT() asm volatile("cp.async.commit_group;" ::: "memory")
#define CP_WAIT1()  asm volatile("cp.async.wait_group 1;" ::: "memory")
#define CP_WAIT0()  asm volatile("cp.async.wait_group 0;" ::: "memory")

__device__ __forceinline__ void mma_bf16(float* c, uint32_t a0, uint32_t a1, uint32_t a2, uint32_t a3,
                                         uint32_t b0, uint32_t b1) {
    asm volatile("mma.sync.aligned.m16n8k16.row.col.f32.bf16.bf16.f32 "
                 "{%0,%1,%2,%3}, {%4,%5,%6,%7}, {%8,%9}, {%0,%1,%2,%3};"
                 : "+f"(c[0]), "+f"(c[1]), "+f"(c[2]), "+f"(c[3])
                 : "r"(a0), "r"(a1), "r"(a2), "r"(a3), "r"(b0), "r"(b1));
}
__device__ __forceinline__ void ldsm4(uint32_t* r, uint32_t addr) {
    asm volatile("ldmatrix.sync.aligned.m8n8.x4.shared.b16 {%0,%1,%2,%3}, [%4];"
                 : "=r"(r[0]), "=r"(r[1]), "=r"(r[2]), "=r"(r[3]) : "r"(addr));
}

// ---------------- fused weight transpose+split (also zeroes g_deg) ----------------
#define WS1 (DIN * DH)
#define WS2 (DH * HEADS * DH)
#define WS3 (HEADS * DH * DH)
#define WS4 (DH * DIN)
__global__ void k_wsplitall(const float* __restrict__ Wp, const float* __restrict__ W1,
                            const float* __restrict__ W2, const float* __restrict__ Wd,
                            __nv_bfloat16* __restrict__ wph, __nv_bfloat16* __restrict__ wpl,
                            __nv_bfloat16* __restrict__ w1h, __nv_bfloat16* __restrict__ w1l,
                            __nv_bfloat16* __restrict__ w2h, __nv_bfloat16* __restrict__ w2l,
                            __nv_bfloat16* __restrict__ wdh, __nv_bfloat16* __restrict__ wdl) {
    int i = blockIdx.x * blockDim.x + threadIdx.x;
    if (i < NN) g_deg[i] = 0;
    const float* W; __nv_bfloat16 *bh, *bl; int K, N, j;
    if (i < WS1)                         { W = Wp; bh = wph; bl = wpl; K = DIN; N = DH;         j = i; }
    else if (i < WS1 + WS2)              { W = W1; bh = w1h; bl = w1l; K = DH;  N = HEADS * DH; j = i - WS1; }
    else if (i < WS1 + WS2 + WS3)        { W = W2; bh = w2h; bl = w2l; K = HEADS * DH; N = DH;  j = i - WS1 - WS2; }
    else if (i < WS1 + WS2 + WS3 + WS4)  { W = Wd; bh = wdh; bl = wdl; K = DH;  N = DIN;        j = i - WS1 - WS2 - WS3; }
    else return;
    int k = j / N, n = j - k * N;
    float v = W[j];
    __nv_bfloat16 h = __float2bfloat16(v);
    bh[(size_t)n * K + k] = h;
    bl[(size_t)n * K + k] = __float2bfloat16(v - __bfloat162float(h));
}

// ---------------- fused input split + edge degree count ----------------
__device__ __forceinline__ void split4(const float4 v, __nv_bfloat16* hi, __nv_bfloat16* lo, size_t i4) {
    __nv_bfloat162 h01, h23, l01, l23;
    h01.x = __float2bfloat16(v.x); l01.x = __float2bfloat16(v.x - __bfloat162float(h01.x));
    h01.y = __float2bfloat16(v.y); l01.y = __float2bfloat16(v.y - __bfloat162float(h01.y));
    h23.x = __float2bfloat16(v.z); l23.x = __float2bfloat16(v.z - __bfloat162float(h23.x));
    h23.y = __float2bfloat16(v.w); l23.y = __float2bfloat16(v.w - __bfloat162float(h23.y));
    ((__nv_bfloat162*)hi)[i4 * 2] = h01; ((__nv_bfloat162*)hi)[i4 * 2 + 1] = h23;
    ((__nv_bfloat162*)lo)[i4 * 2] = l01; ((__nv_bfloat162*)lo)[i4 * 2 + 1] = l23;
}

#define N4 (NN * DIN / 4)
__global__ void k_splitall(const float* __restrict__ x, const float* __restrict__ g,
                           const int* __restrict__ ei,
                           __nv_bfloat16* __restrict__ hi, __nv_bfloat16* __restrict__ lo) {
    int i = blockIdx.x * blockDim.x + threadIdx.x;
    if (i < EE) atomicAdd(&g_deg[ei[EE + i]], 1);    // deg zeroed by k_wsplitall (prior kernel)
    if (i < N4) {
        split4(((const float4*)x)[i], hi, lo, i);
    } else if (i < 2 * N4) {
        int j = i - N4;
        split4(((const float4*)g)[j], hi + (size_t)NN * DIN, lo + (size_t)NN * DIN, j);
    }
}

// ---------------- shuffle-based scan (2 barriers) ----------------
__global__ void k_scan() {
    __shared__ int wsum[32];
    const int CH = 10;                               // 1024*10 >= NN
    int tid = threadIdx.x, lane = tid & 31, wid = tid >> 5;
    int base = tid * CH;
    int pref[CH];
    int s = 0;
#pragma unroll
    for (int j = 0; j < CH; j++) {
        int idx = base + j;
        pref[j] = (idx < NN) ? g_deg[idx] + 1 : 0;
        s += pref[j];
    }
    int sc = s;                                      // warp inclusive scan
#pragma unroll
    for (int o = 1; o < 32; o <<= 1) {
        int t = __shfl_up_sync(0xffffffffu, sc, o);
        if (lane >= o) sc += t;
    }
    if (lane == 31) wsum[wid] = sc;
    __syncthreads();
    if (wid == 0) {
        int w = wsum[lane];
#pragma unroll
        for (int o = 1; o < 32; o <<= 1) {
            int t = __shfl_up_sync(0xffffffffu, w, o);
            if (lane >= o) w += t;
        }
        wsum[lane] = w;
    }
    __syncthreads();
    int run = sc - s + (wid ? wsum[wid - 1] : 0);    // exclusive prefix
#pragma unroll
    for (int j = 0; j < CH; j++) {
        int idx = base + j;
        if (idx < NN) { g_off[idx] = run; g_cur[idx] = run; run += pref[j]; }
    }
    if (tid == 1023) g_off[NN] = run;
}

__global__ void k_fill(const int* __restrict__ ei) {
    int i = blockIdx.x * blockDim.x + threadIdx.x;
    if (i < EE) {
        int d = ei[EE + i];
        g_csr[atomicAdd(&g_cur[d], 1)] = ei[i];
    } else if (i < TE) {
        int n = i - EE;
        g_csr[atomicAdd(&g_cur[n], 1)] = n;
    }
}

// ---------------- mma.sync bf16x3 GEMM (BM=64, occ 2) + fused attn dots + splitRow epilogue ----------------
#define RS_B   80
#define B_B    10240
#define BM     64
#define A_B    (BM * RS_B)
#define STG    (2 * A_B + 2 * B_B)
#define GSMEM  (2 * STG)          // 61440

__global__ __launch_bounds__(256, 2) void k_gemm_mma(
    const __nv_bfloat16* __restrict__ Ahi, const __nv_bfloat16* __restrict__ Alo,
    const __nv_bfloat16* __restrict__ Bhi, const __nv_bfloat16* __restrict__ Blo,
    const float* __restrict__ bias,
    float* __restrict__ Cf, __nv_bfloat16* __restrict__ Chi, __nv_bfloat16* __restrict__ Clo,
    const float* __restrict__ attS, const float* __restrict__ attD,
    float* __restrict__ outS, float* __restrict__ outD,
    int M, int K, int Nc, int splitRow)
{
    constexpr int MT = 2;
    extern __shared__ char smem[];
    const uint32_t sb = smem_u32(smem);
    const int tid = threadIdx.x, wid = tid >> 5, lane = tid & 31;
    const int gid = lane >> 2, tig = lane & 3;
    const int mBase = blockIdx.y * BM, nBase = blockIdx.x * 128;
    const int wrow = (wid & 1) * 32, wcol = (wid >> 1) * 32;

    float acc[MT][4][4];
#pragma unroll
    for (int i = 0; i < MT; i++)
#pragma unroll
        for (int j = 0; j < 4; j++)
#pragma unroll
            for (int q = 0; q < 4; q++) acc[i][j][q] = 0.f;

    const int nchunk = K >> 5;
    const uint32_t aOff = (uint32_t)((wrow + (lane & 15)) * RS_B + (lane >> 4) * 16);
    const uint32_t bOff = (uint32_t)(2 * A_B + (wcol + ((lane >> 4) << 3) + (lane & 7)) * RS_B
                                     + ((lane >> 3) & 1) * 16);

    auto fill = [&](uint32_t bufbase, int k0) {
        {
            int row = tid >> 2, seg = tid & 3;
            uint32_t so = (uint32_t)(row * RS_B + seg * 16);
            int ra = mBase + row; if (ra > M - 1) ra = M - 1;
            size_t ea = (size_t)ra * K + k0 + seg * 8;
            cp16(bufbase + so,       Ahi + ea);
            cp16(bufbase + A_B + so, Alo + ea);
        }
#pragma unroll
        for (int i = tid; i < 512; i += 256) {
            int row = i >> 2, seg = i & 3;
            uint32_t so = (uint32_t)(row * RS_B + seg * 16);
            size_t eb = (size_t)(nBase + row) * K + k0 + seg * 8;
            cp16(bufbase + 2 * A_B + so,       Bhi + eb);
            cp16(bufbase + 2 * A_B + B_B + so, Blo + eb);
        }
    };

    fill(sb, 0);
    CP_COMMIT();

    for (int c = 0; c < nchunk; c++) {
        if (c + 1 < nchunk) {
            fill(sb + ((c + 1) & 1) * STG, (c + 1) << 5);
            CP_COMMIT();
            CP_WAIT1();
        } else {
            CP_WAIT0();
        }
        __syncthreads();

        const uint32_t sbuf = sb + (c & 1) * STG;
        const uint32_t aB = sbuf + aOff;
        const uint32_t bB = sbuf + bOff;

#pragma unroll
        for (int ks = 0; ks < 2; ks++) {
            const uint32_t ko = ks * 32;
            uint32_t ah[MT][4], al[MT][4], bh[4][2], bl[4][2];
#pragma unroll
            for (int mt = 0; mt < MT; mt++) {
                ldsm4(ah[mt], aB + mt * (16 * RS_B) + ko);
                ldsm4(al[mt], aB + A_B + mt * (16 * RS_B) + ko);
            }
#pragma unroll
            for (int p = 0; p < 2; p++) {
                uint32_t r[4];
                ldsm4(r, bB + p * (16 * RS_B) + ko);
                bh[2 * p][0] = r[0]; bh[2 * p][1] = r[1];
                bh[2 * p + 1][0] = r[2]; bh[2 * p + 1][1] = r[3];
                ldsm4(r, bB + B_B + p * (16 * RS_B) + ko);
                bl[2 * p][0] = r[0]; bl[2 * p][1] = r[1];
                bl[2 * p + 1][0] = r[2]; bl[2 * p + 1][1] = r[3];
            }
#pragma unroll
            for (int mt = 0; mt < MT; mt++)
#pragma unroll
                for (int nt = 0; nt < 4; nt++) {
                    mma_bf16(acc[mt][nt], ah[mt][0], ah[mt][1], ah[mt][2], ah[mt][3], bh[nt][0], bh[nt][1]);
                    mma_bf16(acc[mt][nt], ah[mt][0], ah[mt][1], ah[mt][2], ah[mt][3], bl[nt][0], bl[nt][1]);
                    mma_bf16(acc[mt][nt], al[mt][0], al[mt][1], al[mt][2], al[mt][3], bh[nt][0], bh[nt][1]);
                }
        }
        __syncthreads();
    }

    // epilogue (+ optional fused attention dot partials)
    float* sA = (float*)smem;
    float* sD = sA + 4 * BM;
    const int hh = blockIdx.x;

#pragma unroll
    for (int mt = 0; mt < MT; mt++) {
#pragma unroll
        for (int half = 0; half < 2; half++) {
            const int lrow = wrow + mt * 16 + gid + half * 8;
            const int row = mBase + lrow;
            float ps = 0.f, pd = 0.f;
#pragma unroll
            for (int nt = 0; nt < 4; nt++) {
                const int cl = wcol + nt * 8 + tig * 2;
                const int col = nBase + cl;
                float v0 = acc[mt][nt][half * 2 + 0];
                float v1 = acc[mt][nt][half * 2 + 1];
                if (bias) { v0 += bias[col]; v1 += bias[col + 1]; }
                if (attS) {
                    ps += v0 * attS[hh * 128 + cl] + v1 * attS[hh * 128 + cl + 1];
                    pd += v0 * attD[hh * 128 + cl] + v1 * attD[hh * 128 + cl + 1];
                }
                if (row < M) {
                    size_t oi = (size_t)row * Nc + col;
                    if (Cf && row >= splitRow) *(float2*)(Cf + oi) = make_float2(v0, v1);
                    if (Chi && row < splitRow) {
                        __nv_bfloat162 h, l;
                        h.x = __float2bfloat16(v0); l.x = __float2bfloat16(v0 - __bfloat162float(h.x));
                        h.y = __float2bfloat16(v1); l.y = __float2bfloat16(v1 - __bfloat162float(h.y));
                        *(__nv_bfloat162*)(Chi + oi) = h;
                        *(__nv_bfloat162*)(Clo + oi) = l;
                    }
                }
            }
            if (attS) {
                ps += __shfl_xor_sync(0xffffffffu, ps, 1);
                ps += __shfl_xor_sync(0xffffffffu, ps, 2);
                pd += __shfl_xor_sync(0xffffffffu, pd, 1);
                pd += __shfl_xor_sync(0xffffffffu, pd, 2);
                if (tig == 0) {
                    sA[(wid >> 1) * BM + lrow] = ps;
                    sD[(wid >> 1) * BM + lrow] = pd;
                }
            }
        }
    }
    if (attS) {
        __syncthreads();
        if (tid < BM) {
            int row = mBase + tid;
            if (row < M) {
                int H = Nc >> 7;
                outS[row * H + hh] = sA[tid] + sA[BM + tid] + sA[2 * BM + tid] + sA[3 * BM + tid];
                outD[row * H + hh] = sD[tid] + sD[BM + tid] + sD[2 * BM + tid] + sD[3 * BM + tid];
            }
        }
    }
}

__device__ __forceinline__ float lrelu(float e) { return e > 0.f ? e : 0.2f * e; }

// ---------------- GAT1 agg: single-pass softmax + bias + ELU + bf16 split out ----------------
__global__ void k_agg1(const float* __restrict__ hpre, const float* __restrict__ as_,
                       const float* __restrict__ ad_, const float* __restrict__ bias,
                       __nv_bfloat16* __restrict__ ohi, __nv_bfloat16* __restrict__ olo) {
    int gw = (blockIdx.x * blockDim.x + threadIdx.x) >> 5;
    int lane = threadIdx.x & 31;
    if (gw >= NN * HEADS) return;
    int n = gw / HEADS, hh = gw - n * HEADS;
    int beg = g_off[n], end = g_off[n + 1];
    float adn = ad_[gw];

    float ws = 0.f;
    float4 acc = make_float4(0.f, 0.f, 0.f, 0.f);
    const float4* h4 = (const float4*)hpre;
    for (int i = beg; i < end; i++) {
        int s = g_csr[i];
        float ex = __expf(lrelu(as_[s * HEADS + hh] + adn));
        ws += ex;
        float4 v = h4[(size_t)(s * HEADS + hh) * 32 + lane];
        acc.x += ex * v.x; acc.y += ex * v.y; acc.z += ex * v.z; acc.w += ex * v.w;
    }
    float inv = 1.f / (ws + 1e-16f);
    float4 b = ((const float4*)bias)[hh * 32 + lane];
    float4 o;
    o.x = acc.x * inv + b.x; o.y = acc.y * inv + b.y;
    o.z = acc.z * inv + b.z; o.w = acc.w * inv + b.w;
    o.x = o.x > 0.f ? o.x : expm1f(o.x);
    o.y = o.y > 0.f ? o.y : expm1f(o.y);
    o.z = o.z > 0.f ? o.z : expm1f(o.z);
    o.w = o.w > 0.f ? o.w : expm1f(o.w);
    size_t oi = (size_t)gw * 128 + lane * 4;
    __nv_bfloat162 h01, h23, l01, l23;
    h01.x = __float2bfloat16(o.x); l01.x = __float2bfloat16(o.x - __bfloat162float(h01.x));
    h01.y = __float2bfloat16(o.y); l01.y = __float2bfloat16(o.y - __bfloat162float(h01.y));
    h23.x = __float2bfloat16(o.z); l23.x = __float2bfloat16(o.z - __bfloat162float(h23.x));
    h23.y = __float2bfloat16(o.w); l23.y = __float2bfloat16(o.w - __bfloat162float(h23.y));
    *(__nv_bfloat162*)(ohi + oi) = h01; *(__nv_bfloat162*)(ohi + oi + 2) = h23;
    *(__nv_bfloat162*)(olo + oi) = l01; *(__nv_bfloat162*)(olo + oi + 2) = l23;
}

// ---------------- GAT2 agg: single-pass softmax + bias + beta*gp + bf16 split out ----------------
__global__ void k_agg2(const float* __restrict__ hpre, const float* __restrict__ as_,
                       const float* __restrict__ ad_, const float* __restrict__ bias,
                       const float* __restrict__ gp, const float* __restrict__ beta,
                       __nv_bfloat16* __restrict__ ohi, __nv_bfloat16* __restrict__ olo) {
    int n = (blockIdx.x * blockDim.x + threadIdx.x) >> 5;
    int lane = threadIdx.x & 31;
    if (n >= NN) return;
    int beg = g_off[n], end = g_off[n + 1];
    float adn = ad_[n];

    float ws = 0.f;
    float4 acc = make_float4(0.f, 0.f, 0.f, 0.f);
    const float4* h4 = (const float4*)hpre;
    for (int i = beg; i < end; i++) {
        int s = g_csr[i];
        float ex = __expf(lrelu(as_[s] + adn));
        ws += ex;
        float4 v = h4[(size_t)s * 32 + lane];
        acc.x += ex * v.x; acc.y += ex * v.y; acc.z += ex * v.z; acc.w += ex * v.w;
    }
    float inv = 1.f / (ws + 1e-16f);
    float bt = *beta;
    float4 b = ((const float4*)bias)[lane];
    float4 gv = ((const float4*)gp)[(size_t)n * 32 + lane];
    float4 o;
    o.x = acc.x * inv + b.x + bt * gv.x;
    o.y = acc.y * inv + b.y + bt * gv.y;
    o.z = acc.z * inv + b.z + bt * gv.z;
    o.w = acc.w * inv + b.w + bt * gv.w;
    size_t oi = (size_t)n * 128 + lane * 4;
    __nv_bfloat162 h01, h23, l01, l23;
    h01.x = __float2bfloat16(o.x); l01.x = __float2bfloat16(o.x - __bfloat162float(h01.x));
    h01.y = __float2bfloat16(o.y); l01.y = __float2bfloat16(o.y - __bfloat162float(h01.y));
    h23.x = __float2bfloat16(o.z); l23.x = __float2bfloat16(o.z - __bfloat162float(h23.x));
    h23.y = __float2bfloat16(o.w); l23.y = __float2bfloat16(o.w - __bfloat162float(h23.y));
    *(__nv_bfloat162*)(ohi + oi) = h01; *(__nv_bfloat162*)(ohi + oi + 2) = h23;
    *(__nv_bfloat162*)(olo + oi) = l01; *(__nv_bfloat162*)(olo + oi + 2) = l23;
}

// ---------------- launch ----------------
extern "C" void kernel_launch(void* const* d_in, const int* in_sizes, int n_in,
                              void* d_out, int out_size) {
    const float* x      = (const float*)d_in[0];
    const int*   ei     = (const int*)  d_in[1];
    const float* g      = (const float*)d_in[2];
    const float* proj_W = (const float*)d_in[3];
    const float* proj_b = (const float*)d_in[4];
    const float* g1_W   = (const float*)d_in[5];
    const float* g1_as  = (const float*)d_in[6];
    const float* g1_ad  = (const float*)d_in[7];
    const float* g1_b   = (const float*)d_in[8];
    const float* g2_W   = (const float*)d_in[9];
    const float* g2_as  = (const float*)d_in[10];
    const float* g2_ad  = (const float*)d_in[11];
    const float* g2_b   = (const float*)d_in[12];
    const float* dec_W  = (const float*)d_in[13];
    const float* dec_b  = (const float*)d_in[14];
    const float* beta   = (const float*)d_in[15];
    float* out = (float*)d_out;

    __nv_bfloat16 *xg_hi, *xg_lo, *xpgp_hi, *xpgp_lo, *h1_hi, *h1_lo, *h2_hi, *h2_lo;
    __nv_bfloat16 *wp_hi, *wp_lo, *w1_hi, *w1_lo, *w2_hi, *w2_lo, *wd_hi, *wd_lo;
    float *xpgp, *h1pre, *h2pre, *as1, *ad1, *as2, *ad2;
    cudaGetSymbolAddress((void**)&xg_hi,   g_xg_hi);   cudaGetSymbolAddress((void**)&xg_lo,   g_xg_lo);
    cudaGetSymbolAddress((void**)&xpgp,    g_xpgp);
    cudaGetSymbolAddress((void**)&xpgp_hi, g_xpgp_hi); cudaGetSymbolAddress((void**)&xpgp_lo, g_xpgp_lo);
    cudaGetSymbolAddress((void**)&h1pre,   g_h1pre);
    cudaGetSymbolAddress((void**)&h1_hi,   g_h1_hi);   cudaGetSymbolAddress((void**)&h1_lo,   g_h1_lo);
    cudaGetSymbolAddress((void**)&h2pre,   g_h2pre);
    cudaGetSymbolAddress((void**)&h2_hi,   g_h2_hi);   cudaGetSymbolAddress((void**)&h2_lo,   g_h2_lo);
    cudaGetSymbolAddress((void**)&wp_hi,   g_wp_hi);   cudaGetSymbolAddress((void**)&wp_lo,   g_wp_lo);
    cudaGetSymbolAddress((void**)&w1_hi,   g_w1_hi);   cudaGetSymbolAddress((void**)&w1_lo,   g_w1_lo);
    cudaGetSymbolAddress((void**)&w2_hi,   g_w2_hi);   cudaGetSymbolAddress((void**)&w2_lo,   g_w2_lo);
    cudaGetSymbolAddress((void**)&wd_hi,   g_wd_hi);   cudaGetSymbolAddress((void**)&wd_lo,   g_wd_lo);
    cudaGetSymbolAddress((void**)&as1, g_as1); cudaGetSymbolAddress((void**)&ad1, g_ad1);
    cudaGetSymbolAddress((void**)&as2, g_as2); cudaGetSymbolAddress((void**)&ad2, g_ad2);

    cudaFuncSetAttribute(k_gemm_mma, cudaFuncAttributeMaxDynamicSharedMemorySize, GSMEM);

    // prep: weight split (+deg zero) -> input split (+edge count) -> scan -> fill
    k_wsplitall<<<(WS1 + WS2 + WS3 + WS4 + 255) / 256, 256>>>(
        proj_W, g1_W, g2_W, dec_W, wp_hi, wp_lo, w1_hi, w1_lo, w2_hi, w2_lo, wd_hi, wd_lo);
    k_splitall<<<(2 * N4 + 255) / 256, 256>>>(x, g, ei, xg_hi, xg_lo);
    k_scan<<<1, 1024>>>();
    k_fill<<<(TE + 255) / 256, 256>>>(ei);

    // proj (batched x|g): rows<NN write hi/lo only, rows>=NN write f32 only
    k_gemm_mma<<<dim3(1, (MP + BM - 1) / BM), 256, GSMEM>>>(
        xg_hi, xg_lo, wp_hi, wp_lo, proj_b, xpgp, xpgp_hi, xpgp_lo,
        nullptr, nullptr, nullptr, nullptr, MP, DIN, DH, NN);

    // GAT1: [10000,128] @ [128,512] + fused attention dots
    k_gemm_mma<<<dim3(HEADS * DH / 128, (NN + BM - 1) / BM), 256, GSMEM>>>(
        xpgp_hi, xpgp_lo, w1_hi, w1_lo, nullptr, h1pre, nullptr, nullptr,
        g1_as, g1_ad, as1, ad1, NN, DH, HEADS * DH, 0);
    k_agg1<<<(NN * HEADS * 32 + 255) / 256, 256>>>(h1pre, as1, ad1, g1_b, h1_hi, h1_lo);

    // GAT2: [10000,512] @ [512,128] + fused attention dots
    k_gemm_mma<<<dim3(1, (NN + BM - 1) / BM), 256, GSMEM>>>(
        h1_hi, h1_lo, w2_hi, w2_lo, nullptr, h2pre, nullptr, nullptr,
        g2_as, g2_ad, as2, ad2, NN, HEADS * DH, DH, 0);
    k_agg2<<<(NN * 32 + 255) / 256, 256>>>(h2pre, as2, ad2, g2_b, xpgp + (size_t)NN * DH, beta, h2_hi, h2_lo);

    // decoder: [10000,128] @ [128,768]
    k_gemm_mma<<<dim3(DIN / 128, (NN + BM - 1) / BM), 256, GSMEM>>>(
        h2_hi, h2_lo, wd_hi, wd_lo, dec_b, out, nullptr, nullptr,
        nullptr, nullptr, nullptr, nullptr, NN, DH, DIN, 0);
}